// round 3
// baseline (speedup 1.0000x reference)
#include <cuda_runtime.h>
#include <math.h>

// ---------------- problem constants ----------------
#define BB    2
#define NTOK  4096
#define KTOK  144
#define DIMM  512
#define NHEAD 8
#define DH    64
#define QKVW  1536
#define MLPW  2048
#define DEPTHL 4
#define RTOT  (BB*NTOK + BB*KTOK + BB)   // 8482
#define KROW0 (BB*NTOK)                  // 8192
#define CROW0 (BB*NTOK + BB*KTOK)        // 8480
#define NEGBIG (-1e9f)
#define ATT_SCALE 0.125f                 // 64^-0.5

// ---------------- scratch (device globals; no malloc allowed) ----------------
__device__ float d_cur[RTOT*DIMM];
__device__ float d_lnb[RTOT*DIMM];
__device__ float d_qkvb[RTOT*QKVW];
__device__ float d_att[RTOT*DIMM];
__device__ float d_ff[RTOT*MLPW];

// ---------------- reduction helpers (256-thread blocks) ----------------
__device__ __forceinline__ float blockReduceSum256(float v) {
    __shared__ float sh[8];
    int lane = threadIdx.x & 31, w = threadIdx.x >> 5;
    #pragma unroll
    for (int o = 16; o; o >>= 1) v += __shfl_down_sync(0xffffffffu, v, o);
    if (lane == 0) sh[w] = v;
    __syncthreads();
    float r;
    if (threadIdx.x < 8) r = sh[threadIdx.x]; else r = 0.f;
    if (w == 0) {
        #pragma unroll
        for (int o = 4; o; o >>= 1) r += __shfl_down_sync(0xffu, r, o);
        if (lane == 0) sh[0] = r;
    }
    __syncthreads();
    r = sh[0];
    __syncthreads();
    return r;
}

__device__ __forceinline__ float blockReduceMax256(float v) {
    __shared__ float sh[8];
    int lane = threadIdx.x & 31, w = threadIdx.x >> 5;
    #pragma unroll
    for (int o = 16; o; o >>= 1) v = fmaxf(v, __shfl_down_sync(0xffffffffu, v, o));
    if (lane == 0) sh[w] = v;
    __syncthreads();
    float r;
    if (threadIdx.x < 8) r = sh[threadIdx.x]; else r = -INFINITY;
    if (w == 0) {
        #pragma unroll
        for (int o = 4; o; o >>= 1) r = fmaxf(r, __shfl_down_sync(0xffu, r, o));
        if (lane == 0) sh[0] = r;
    }
    __syncthreads();
    r = sh[0];
    __syncthreads();
    return r;
}

// ---------------- init: concat x / kx / clst into cur ----------------
__global__ void k_init(const float* __restrict__ x, const float* __restrict__ kx,
                       const float* __restrict__ clst) {
    int idx = blockIdx.x * blockDim.x + threadIdx.x;
    if (idx >= RTOT * DIMM) return;
    int row = idx >> 9;
    int d   = idx & 511;
    float v;
    if (row < KROW0)        v = x[idx];
    else if (row < CROW0)   v = kx[(row - KROW0) * DIMM + d];
    else                    v = clst[(row - CROW0) * DIMM + d];
    d_cur[idx] = v;
}

// ---------------- LayerNorm: one block per row, 256 threads ----------------
// MODE 0: in = d_cur, out = d_cur (destructive LN1)
// MODE 1: in = d_cur, out = d_lnb (LN2)
template<int MODE>
__global__ void k_layernorm(const float* __restrict__ g, const float* __restrict__ bp) {
    int row = blockIdx.x;
    int t = threadIdx.x;
    const float* r = d_cur + (size_t)row * DIMM;
    float v0 = r[t];
    float v1 = r[t + 256];
    float s  = blockReduceSum256(v0 + v1);
    float mean = s * (1.0f / DIMM);
    float d0 = v0 - mean, d1 = v1 - mean;
    float sq = blockReduceSum256(d0 * d0 + d1 * d1);
    float inv = rsqrtf(sq * (1.0f / DIMM) + 1e-5f);
    float* o = (MODE == 0 ? d_cur : d_lnb) + (size_t)row * DIMM;
    o[t]       = d0 * inv * g[t]       + bp[t];
    o[t + 256] = d1 * inv * g[t + 256] + bp[t + 256];
}

// ---------------- SGEMM: C[M,N] = A[M,K] @ B[K,N]  (+epilogue) ----------------
// EPI 0: plain   EPI 1: +bias, +residual   EPI 2: +bias, exact GELU
#define GBM 128
#define GBN 128
#define GBK 8
#define GTM 8
#define GTN 8

__device__ __forceinline__ float gelu_exact(float v) {
    return 0.5f * v * (1.0f + erff(v * 0.70710678118654752f));
}

template<int EPI>
__global__ __launch_bounds__(256, 2)
void k_sgemm(int M, int N, int K,
             const float* __restrict__ A, const float* __restrict__ B,
             const float* __restrict__ bias, const float* __restrict__ res,
             float* __restrict__ C) {
    __shared__ float As[GBK][GBM];
    __shared__ float Bs[GBK][GBN];
    int tid = threadIdx.x;
    int m0 = blockIdx.y * GBM, n0 = blockIdx.x * GBN;
    int arow = tid >> 1, acol = (tid & 1) * 4;     // A tile: 128x8
    int brow = tid >> 5, bcol = (tid & 31) * 4;    // B tile: 8x128
    int tx = tid & 15, ty = tid >> 4;
    float acc[GTM][GTN];
    #pragma unroll
    for (int i = 0; i < GTM; i++)
        #pragma unroll
        for (int j = 0; j < GTN; j++) acc[i][j] = 0.f;

    for (int k0 = 0; k0 < K; k0 += GBK) {
        float4 av;
        if (m0 + arow < M) av = *(const float4*)&A[(size_t)(m0 + arow) * K + k0 + acol];
        else av = make_float4(0.f, 0.f, 0.f, 0.f);
        As[acol + 0][arow] = av.x;
        As[acol + 1][arow] = av.y;
        As[acol + 2][arow] = av.z;
        As[acol + 3][arow] = av.w;
        *(float4*)&Bs[brow][bcol] = *(const float4*)&B[(size_t)(k0 + brow) * N + n0 + bcol];
        __syncthreads();
        #pragma unroll
        for (int kk = 0; kk < GBK; kk++) {
            float ra[GTM], rb[GTN];
            #pragma unroll
            for (int i = 0; i < GTM; i++) ra[i] = As[kk][ty * GTM + i];
            #pragma unroll
            for (int j = 0; j < GTN; j++) rb[j] = Bs[kk][tx * GTN + j];
            #pragma unroll
            for (int i = 0; i < GTM; i++)
                #pragma unroll
                for (int j = 0; j < GTN; j++) acc[i][j] += ra[i] * rb[j];
        }
        __syncthreads();
    }

    #pragma unroll
    for (int i = 0; i < GTM; i++) {
        int row = m0 + ty * GTM + i;
        if (row >= M) continue;
        #pragma unroll
        for (int j = 0; j < GTN; j++) {
            int col = n0 + tx * GTN + j;
            float v = acc[i][j];
            if (EPI >= 1) v += bias[col];
            if (EPI == 2) v = gelu_exact(v);
            if (EPI == 1) v += res[(size_t)row * N + col];
            C[(size_t)row * N + col] = v;
        }
    }
}

// ---------------- patch -> kernel attention ----------------
// grid (128, 8, 2): 32 queries per block.  k=144 keys staged in smem.
#define PAD 65
__global__ void k_attn_patch(const float* __restrict__ rd,
                             const float* __restrict__ mask, const float* __restrict__ kmask,
                             float inv_denom) {
    extern __shared__ float sm[];
    float* Ks = sm;                    // 144*65
    float* Qs = Ks + KTOK * PAD;       // 32*65
    float* Sc = Qs + 32 * PAD;         // 32*144
    int b = blockIdx.z, h = blockIdx.y;
    int i0 = blockIdx.x * 32;
    int tid = threadIdx.x;
    const float* qkv = d_qkvb;

    // stage K (keys of kernel tokens)
    for (int idx = tid; idx < KTOK * DH; idx += 256) {
        int j = idx >> 6, d = idx & 63;
        Ks[j * PAD + d] = qkv[(size_t)(KROW0 + b * KTOK + j) * QKVW + DIMM + h * DH + d];
    }
    // stage Q (patch queries)
    for (int idx = tid; idx < 32 * DH; idx += 256) {
        int i = idx >> 6, d = idx & 63;
        Qs[i * PAD + d] = qkv[(size_t)(b * NTOK + i0 + i) * QKVW + h * DH + d];
    }
    __syncthreads();

    int warp = tid >> 5, lane = tid & 31;
    #pragma unroll
    for (int qi = 0; qi < 4; qi++) {
        int i = warp * 4 + qi;
        float mi = mask[b * NTOK + i0 + i];
        for (int j = lane; j < KTOK; j += 32) {
            float dot = 0.f;
            #pragma unroll
            for (int d = 0; d < DH; d++) dot += Qs[i * PAD + d] * Ks[j * PAD + d];
            float s = (mi * kmask[b * KTOK + j] < 0.5f) ? NEGBIG : dot * ATT_SCALE;
            Sc[i * KTOK + j] = s;
        }
        // warp-level softmax over 144 + decay
        float m = -INFINITY;
        for (int j = lane; j < KTOK; j += 32) m = fmaxf(m, Sc[i * KTOK + j]);
        #pragma unroll
        for (int o = 16; o; o >>= 1) m = fmaxf(m, __shfl_xor_sync(0xffffffffu, m, o));
        float ssum = 0.f;
        for (int j = lane; j < KTOK; j += 32) {
            float e = expf(Sc[i * KTOK + j] - m);
            Sc[i * KTOK + j] = e;
            ssum += e;
        }
        #pragma unroll
        for (int o = 16; o; o >>= 1) ssum += __shfl_xor_sync(0xffffffffu, ssum, o);
        float invs = 1.0f / ssum;
        for (int j = lane; j < KTOK; j += 32) {
            float r = rd[(size_t)b * KTOK * NTOK + (size_t)j * NTOK + i0 + i];
            Sc[i * KTOK + j] *= invs * expf(-r * r * inv_denom);
        }
    }
    __syncthreads();

    // stage V over Ks
    for (int idx = tid; idx < KTOK * DH; idx += 256) {
        int j = idx >> 6, d = idx & 63;
        Ks[j * PAD + d] = qkv[(size_t)(KROW0 + b * KTOK + j) * QKVW + 2 * DIMM + h * DH + d];
    }
    __syncthreads();

    int i = tid >> 3;
    int d0 = (tid & 7) * 8;
    float acc[8] = {0.f,0.f,0.f,0.f,0.f,0.f,0.f,0.f};
    for (int j = 0; j < KTOK; j++) {
        float p = Sc[i * KTOK + j];
        #pragma unroll
        for (int dd = 0; dd < 8; dd++) acc[dd] += p * Ks[j * PAD + d0 + dd];
    }
    size_t row = (size_t)(b * NTOK + i0 + i);
    #pragma unroll
    for (int dd = 0; dd < 8; dd++)
        d_att[row * DIMM + h * DH + d0 + dd] = acc[dd];
}

// ---------------- kernel -> patch attention ----------------
// grid (144, 8, 2): one kernel-token row per block; softmax over n=4096.
__global__ __launch_bounds__(256)
void k_attn_kside(const float* __restrict__ rd,
                  const float* __restrict__ mask, const float* __restrict__ kmask,
                  float inv_denom) {
    __shared__ float Sc[NTOK];
    __shared__ float Qs[DH];
    __shared__ float accs[DH];
    int ik = blockIdx.x, h = blockIdx.y, b = blockIdx.z;
    int tid = threadIdx.x;
    const float* qkv = d_qkvb;
    size_t qrow = (size_t)(KROW0 + b * KTOK + ik);

    if (tid < DH) {
        Qs[tid] = qkv[qrow * QKVW + h * DH + tid];
        accs[tid] = 0.f;
    }
    __syncthreads();

    float kmi = kmask[b * KTOK + ik];
    float lmax = -INFINITY;
    for (int j = tid; j < NTOK; j += 256) {
        const float4* kp = (const float4*)&qkv[(size_t)(b * NTOK + j) * QKVW + DIMM + h * DH];
        float dot = 0.f;
        #pragma unroll
        for (int d4 = 0; d4 < 16; d4++) {
            float4 kv = kp[d4];
            dot += Qs[d4*4+0]*kv.x + Qs[d4*4+1]*kv.y + Qs[d4*4+2]*kv.z + Qs[d4*4+3]*kv.w;
        }
        float s = (mask[b * NTOK + j] * kmi < 0.5f) ? NEGBIG : dot * ATT_SCALE;
        Sc[j] = s;
        lmax = fmaxf(lmax, s);
    }
    float M = blockReduceMax256(lmax);
    float lsum = 0.f;
    for (int j = tid; j < NTOK; j += 256) {
        float e = expf(Sc[j] - M);
        Sc[j] = e;
        lsum += e;
    }
    float S = blockReduceSum256(lsum);
    float invS = 1.0f / S;

    float acc[DH];
    #pragma unroll
    for (int d = 0; d < DH; d++) acc[d] = 0.f;
    const float* rdp = rd + (size_t)b * KTOK * NTOK + (size_t)ik * NTOK;
    for (int j = tid; j < NTOK; j += 256) {
        float r = rdp[j];
        float p = Sc[j] * invS * expf(-r * r * inv_denom);
        const float4* vp = (const float4*)&qkv[(size_t)(b * NTOK + j) * QKVW + 2 * DIMM + h * DH];
        #pragma unroll
        for (int d4 = 0; d4 < 16; d4++) {
            float4 vv = vp[d4];
            acc[d4*4+0] += p * vv.x;
            acc[d4*4+1] += p * vv.y;
            acc[d4*4+2] += p * vv.z;
            acc[d4*4+3] += p * vv.w;
        }
    }
    int lane = tid & 31;
    #pragma unroll
    for (int d = 0; d < DH; d++) {
        float v = acc[d];
        #pragma unroll
        for (int o = 16; o; o >>= 1) v += __shfl_down_sync(0xffffffffu, v, o);
        if (lane == 0) atomicAdd(&accs[d], v);
    }
    __syncthreads();
    if (tid < DH)
        d_att[qrow * DIMM + h * DH + tid] = accs[tid];
}

// ---------------- clst -> kernel attention (no decay) ----------------
__global__ void k_attn_clst(const float* __restrict__ mask,
                            const float* __restrict__ kmask) {
    __shared__ float Qc[DH];
    __shared__ float Sc[KTOK];
    int h = blockIdx.x, b = blockIdx.y;
    int tid = threadIdx.x;
    const float* qkv = d_qkvb;
    size_t qrow = (size_t)(CROW0 + b);
    if (tid < DH) Qc[tid] = qkv[qrow * QKVW + h * DH + tid];
    __syncthreads();
    float m0 = mask[b * NTOK];
    float s = -INFINITY;
    if (tid < KTOK) {
        const float4* kp = (const float4*)&qkv[(size_t)(KROW0 + b * KTOK + tid) * QKVW + DIMM + h * DH];
        float dot = 0.f;
        #pragma unroll
        for (int d4 = 0; d4 < 16; d4++) {
            float4 kv = kp[d4];
            dot += Qc[d4*4+0]*kv.x + Qc[d4*4+1]*kv.y + Qc[d4*4+2]*kv.z + Qc[d4*4+3]*kv.w;
        }
        s = (m0 * kmask[b * KTOK + tid] < 0.5f) ? NEGBIG : dot * ATT_SCALE;
        Sc[tid] = s;
    }
    float M = blockReduceMax256(s);
    float e = 0.f;
    if (tid < KTOK) {
        e = expf(s - M);
        Sc[tid] = e;
    }
    float S = blockReduceSum256(e);
    float invS = 1.0f / S;
    if (tid < DH) {
        float a = 0.f;
        for (int j = 0; j < KTOK; j++)
            a += Sc[j] * qkv[(size_t)(KROW0 + b * KTOK + j) * QKVW + 2 * DIMM + h * DH + tid];
        d_att[qrow * DIMM + h * DH + tid] = a * invS;
    }
}

// ---------------- output writes ----------------
__global__ void k_write_krep(float* __restrict__ out, const float* __restrict__ kmask) {
    int idx = blockIdx.x * blockDim.x + threadIdx.x;
    if (idx >= BB * KTOK * DIMM) return;
    int d = idx & 511;
    int row = idx >> 9;                // b*144 + j
    float km = kmask[row];
    float v = (km < 0.5f) ? 0.f : d_cur[(size_t)(KROW0 + row) * DIMM + d];
    out[idx] = v;
}

__global__ void k_write_clst(float* __restrict__ out) {
    int idx = blockIdx.x * blockDim.x + threadIdx.x;
    if (idx >= BB * DIMM) return;
    int b = idx >> 9, d = idx & 511;
    out[idx] = d_cur[(size_t)(CROW0 + b) * DIMM + d];
}

// ---------------- launcher ----------------
extern "C" void kernel_launch(void* const* d_in, const int* in_sizes, int n_in,
                              void* d_out, int out_size) {
    const float* x     = (const float*)d_in[0];
    const float* kx    = (const float*)d_in[1];
    const float* rd    = (const float*)d_in[2];
    const float* clst  = (const float*)d_in[3];
    const float* mask  = (const float*)d_in[4];
    const float* kmask = (const float*)d_in[5];
    const float* ln1_g = (const float*)d_in[6];
    const float* ln1_b = (const float*)d_in[7];
    const float* w_qkv = (const float*)d_in[8];
    const float* w_out = (const float*)d_in[9];
    const float* b_out = (const float*)d_in[10];
    const float* ln2_g = (const float*)d_in[11];
    const float* ln2_b = (const float*)d_in[12];
    const float* w1    = (const float*)d_in[13];
    const float* b1    = (const float*)d_in[14];
    const float* w2    = (const float*)d_in[15];
    const float* b2    = (const float*)d_in[16];
    float* out = (float*)d_out;

    // Scratch buffer device addresses for SGEMM arguments (host-side symbol
    // lookup is done once per call; capture-legal, not stream-ordered).
    static float *cur = nullptr, *lnb = nullptr, *qkvb = nullptr, *att = nullptr, *ff = nullptr;
    if (!cur) {
        cudaGetSymbolAddress((void**)&cur,  d_cur);
        cudaGetSymbolAddress((void**)&lnb,  d_lnb);
        cudaGetSymbolAddress((void**)&qkvb, d_qkvb);
        cudaGetSymbolAddress((void**)&att,  d_att);
        cudaGetSymbolAddress((void**)&ff,   d_ff);
        int patch_smem = (KTOK * PAD + 32 * PAD + 32 * KTOK) * (int)sizeof(float); // 64192
        cudaFuncSetAttribute(k_attn_patch, cudaFuncAttributeMaxDynamicSharedMemorySize, patch_smem);
    }
    int patch_smem = (KTOK * PAD + 32 * PAD + 32 * KTOK) * (int)sizeof(float);

    int mtiles = (RTOT + GBM - 1) / GBM;  // 67

    k_init<<<(RTOT * DIMM + 255) / 256, 256>>>(x, kx, clst);

    for (int l = 0; l < DEPTHL; l++) {
        float inv_denom = 1.0f / (64.0f * (float)(1 << l));   // 1/(2*NPK*2^l)

        // LN1 (destructive: residual base is the normalized value)
        k_layernorm<0><<<RTOT, 256>>>(ln1_g + l * DIMM, ln1_b + l * DIMM);

        // QKV projection over all 8482 rows
        k_sgemm<0><<<dim3(QKVW / GBN, mtiles), 256>>>(RTOT, QKVW, DIMM,
                cur, w_qkv + (size_t)l * DIMM * QKVW, nullptr, nullptr, qkvb);

        // attentions -> merged-head buffer
        k_attn_patch<<<dim3(NTOK / 32, NHEAD, BB), 256, patch_smem>>>(
                rd, mask, kmask, inv_denom);
        k_attn_kside<<<dim3(KTOK, NHEAD, BB), 256>>>(
                rd, mask, kmask, inv_denom);
        k_attn_clst<<<dim3(NHEAD, BB), 256>>>(mask, kmask);

        // out projection + residual into cur
        k_sgemm<1><<<dim3(DIMM / GBN, mtiles), 256>>>(RTOT, DIMM, DIMM,
                att, w_out + (size_t)l * DIMM * DIMM, b_out + l * DIMM, cur, cur);

        // FFN
        k_layernorm<1><<<RTOT, 256>>>(ln2_g + l * DIMM, ln2_b + l * DIMM);
        k_sgemm<2><<<dim3(MLPW / GBN, mtiles), 256>>>(RTOT, MLPW, DIMM,
                lnb, w1 + (size_t)l * DIMM * MLPW, b1 + l * MLPW, nullptr, ff);
        k_sgemm<1><<<dim3(DIMM / GBN, mtiles), 256>>>(RTOT, DIMM, MLPW,
                ff, w2 + (size_t)l * MLPW * DIMM, b2 + l * DIMM, cur, cur);

        // masked k_rep for this layer
        k_write_krep<<<(BB * KTOK * DIMM + 255) / 256, 256>>>(
                out + (size_t)l * BB * KTOK * DIMM, kmask);
    }

    k_write_clst<<<(BB * DIMM + 255) / 256, 256>>>(out + (size_t)DEPTHL * BB * KTOK * DIMM);
}

// round 5
// speedup vs baseline: 1.2334x; 1.2334x over previous
#include <cuda_runtime.h>
#include <cuda_bf16.h>
#include <math.h>
#include <stdint.h>

// ---------------- problem constants ----------------
#define BB    2
#define NTOK  4096
#define KTOK  144
#define DIMM  512
#define NHEAD 8
#define DH    64
#define QKVW  1536
#define MLPW  2048
#define DEPTHL 4
#define RTOT  (BB*NTOK + BB*KTOK + BB)   // 8482
#define KROW0 (BB*NTOK)                  // 8192
#define CROW0 (BB*NTOK + BB*KTOK)        // 8480
#define NEGBIG (-1e9f)
#define ATT_SCALE 0.125f                 // 64^-0.5

// ---------------- scratch (device globals; no malloc allowed) ----------------
__device__ float d_cur[RTOT*DIMM];
__device__ float d_lnb[RTOT*DIMM];
__device__ float d_qkvb[RTOT*QKVW];
__device__ float d_att[RTOT*DIMM];
__device__ float d_ff[RTOT*MLPW];
// split-bf16 operands
__device__ __align__(128) __nv_bfloat16 d_act2[RTOT*2*MLPW];          // up to [RTOT, 4096]
__device__ __align__(128) __nv_bfloat16 d_wqkv2[DEPTHL*QKVW*2*DIMM];  // [l][1536][1024]
__device__ __align__(128) __nv_bfloat16 d_wout2[DEPTHL*DIMM*2*DIMM];  // [l][512][1024]
__device__ __align__(128) __nv_bfloat16 d_w12[DEPTHL*MLPW*2*DIMM];    // [l][2048][1024]
__device__ __align__(128) __nv_bfloat16 d_w22[DEPTHL*DIMM*2*MLPW];    // [l][512][4096]

// ---------------- helpers ----------------
__device__ __forceinline__ uint32_t smem_u32(const void* p) {
    uint32_t a;
    asm("{ .reg .u64 t; cvta.to.shared.u64 t, %1; cvt.u32.u64 %0, t; }" : "=r"(a) : "l"(p));
    return a;
}
#define SW128(x) ((x) ^ (((x) >> 3) & 0x70))

__device__ __forceinline__ void ldsm4(uint32_t* r, uint32_t addr) {
    asm volatile("ldmatrix.sync.aligned.m8n8.x4.shared.b16 {%0,%1,%2,%3}, [%4];"
        : "=r"(r[0]), "=r"(r[1]), "=r"(r[2]), "=r"(r[3]) : "r"(addr));
}
__device__ __forceinline__ void mma16816(float* c,
        uint32_t a0, uint32_t a1, uint32_t a2, uint32_t a3,
        uint32_t b0, uint32_t b1) {
    asm volatile("mma.sync.aligned.m16n8k16.row.col.f32.bf16.bf16.f32 "
        "{%0,%1,%2,%3}, {%4,%5,%6,%7}, {%8,%9}, {%0,%1,%2,%3};"
        : "+f"(c[0]), "+f"(c[1]), "+f"(c[2]), "+f"(c[3])
        : "r"(a0), "r"(a1), "r"(a2), "r"(a3), "r"(b0), "r"(b1));
}

// ---------------- reduction helpers (256-thread blocks) ----------------
__device__ __forceinline__ float blockReduceSum256(float v) {
    __shared__ float sh[8];
    int lane = threadIdx.x & 31, w = threadIdx.x >> 5;
    #pragma unroll
    for (int o = 16; o; o >>= 1) v += __shfl_down_sync(0xffffffffu, v, o);
    if (lane == 0) sh[w] = v;
    __syncthreads();
    float r;
    if (threadIdx.x < 8) r = sh[threadIdx.x]; else r = 0.f;
    if (w == 0) {
        #pragma unroll
        for (int o = 4; o; o >>= 1) r += __shfl_down_sync(0xffu, r, o);
        if (lane == 0) sh[0] = r;
    }
    __syncthreads();
    r = sh[0];
    __syncthreads();
    return r;
}

__device__ __forceinline__ float blockReduceMax256(float v) {
    __shared__ float sh[8];
    int lane = threadIdx.x & 31, w = threadIdx.x >> 5;
    #pragma unroll
    for (int o = 16; o; o >>= 1) v = fmaxf(v, __shfl_down_sync(0xffffffffu, v, o));
    if (lane == 0) sh[w] = v;
    __syncthreads();
    float r;
    if (threadIdx.x < 8) r = sh[threadIdx.x]; else r = -INFINITY;
    if (w == 0) {
        #pragma unroll
        for (int o = 4; o; o >>= 1) r = fmaxf(r, __shfl_down_sync(0xffu, r, o));
        if (lane == 0) sh[0] = r;
    }
    __syncthreads();
    r = sh[0];
    __syncthreads();
    return r;
}

// ---------------- init: concat x / kx / clst into cur ----------------
__global__ void k_init(const float* __restrict__ x, const float* __restrict__ kx,
                       const float* __restrict__ clst) {
    int idx = blockIdx.x * blockDim.x + threadIdx.x;
    if (idx >= RTOT * DIMM) return;
    int row = idx >> 9;
    int d   = idx & 511;
    float v;
    if (row < KROW0)        v = x[idx];
    else if (row < CROW0)   v = kx[(row - KROW0) * DIMM + d];
    else                    v = clst[(row - CROW0) * DIMM + d];
    d_cur[idx] = v;
}

// ---------------- LayerNorm: one block per row, 256 threads ----------------
template<int MODE>
__global__ void k_layernorm(const float* __restrict__ g, const float* __restrict__ bp) {
    int row = blockIdx.x;
    int t = threadIdx.x;
    const float* r = d_cur + (size_t)row * DIMM;
    float v0 = r[t];
    float v1 = r[t + 256];
    float s  = blockReduceSum256(v0 + v1);
    float mean = s * (1.0f / DIMM);
    float d0 = v0 - mean, d1 = v1 - mean;
    float sq = blockReduceSum256(d0 * d0 + d1 * d1);
    float inv = rsqrtf(sq * (1.0f / DIMM) + 1e-5f);
    float* o = (MODE == 0 ? d_cur : d_lnb) + (size_t)row * DIMM;
    o[t]       = d0 * inv * g[t]       + bp[t];
    o[t + 256] = d1 * inv * g[t + 256] + bp[t + 256];
}

// ---------------- split conversions ----------------
// activations: X [RTOT, KK] fp32 -> X2 [RTOT, 2*KK] bf16 ([hi | lo])
template<int KK>
__global__ void k_asplit(const float* __restrict__ X, __nv_bfloat16* __restrict__ X2) {
    int idx = blockIdx.x * blockDim.x + threadIdx.x;
    if (idx >= RTOT * KK) return;
    int m = idx / KK, k = idx - m * KK;
    float v = X[idx];
    __nv_bfloat16 hi = __float2bfloat16(v);
    float lo = v - __bfloat162float(hi);
    size_t o = (size_t)m * (2 * KK) + k;
    X2[o]      = hi;
    X2[o + KK] = __float2bfloat16(lo);
}

// weights: W [K, N] fp32 -> WT [N, 2K] bf16 (transpose + split)
__global__ void k_wsplit(const float* __restrict__ W, __nv_bfloat16* __restrict__ WT,
                         int K, int N) {
    __shared__ float t[32][33];
    int k0 = blockIdx.y * 32, n0 = blockIdx.x * 32;
    int tx = threadIdx.x, ty = threadIdx.y;      // block (32,8)
    #pragma unroll
    for (int i = 0; i < 32; i += 8)
        t[ty + i][tx] = W[(size_t)(k0 + ty + i) * N + n0 + tx];
    __syncthreads();
    #pragma unroll
    for (int i = 0; i < 32; i += 8) {
        int n = n0 + ty + i, k = k0 + tx;
        float v = t[tx][ty + i];
        __nv_bfloat16 hi = __float2bfloat16(v);
        float lo = v - __bfloat162float(hi);
        WT[(size_t)n * (2 * K) + k]     = hi;
        WT[(size_t)n * (2 * K) + K + k] = __float2bfloat16(lo);
    }
}

// ---------------- HMMA bf16x3 GEMM ----------------
// C[M,N] = A[M,Kh]*B^T  with split operands A2 [M,2Kh], B2 [N,2Kh] (bf16 hi|lo).
// Virtual K = 3*Kh segments: (hiA,hiB), (hiA,loB), (loA,hiB).
// CTA: 128x128 C tile, 256 thr = 8 warps (4 M x 2 N), warp tile 32x64.
// K-chunk 64 bf16 (128B rows, SW128 swizzle), double-buffered smem.
// EPI 0: plain  EPI 1: +bias,+residual  EPI 2: +bias, exact GELU
#define HG_STAGE 32768                    // A 16KB + B 16KB
#define HG_SMEM  (2 * HG_STAGE)           // 64KB

__device__ __forceinline__ float gelu_exact(float v) {
    return 0.5f * v * (1.0f + erff(v * 0.70710678118654752f));
}

template<int EPI>
__global__ __launch_bounds__(256, 1)
void k_hgemm(int M, int N, int Kh,
             const __nv_bfloat16* __restrict__ A2, const __nv_bfloat16* __restrict__ B2,
             const float* __restrict__ bias, const float* __restrict__ res,
             float* __restrict__ C) {
    extern __shared__ char smem[];
    uint32_t sb = smem_u32(smem);
    int tid = threadIdx.x, wid = tid >> 5, lane = tid & 31;
    int m0 = blockIdx.y * 128, n0 = blockIdx.x * 128;
    int K2 = 2 * Kh;
    int wm = wid & 3, wn = wid >> 2;      // warp tile (32 M, 64 N)

    // global load assignment: thread -> (row r, half) 64 bytes per tile
    int r = tid >> 1, half = tid & 1;
    int bo = r * 128 + half * 64;
    bool arow_ok = (m0 + r) < M;
    const char* arow = (const char*)(A2 + (size_t)(m0 + r) * K2) + half * 64;
    const char* brow = (const char*)(B2 + (size_t)(n0 + r) * K2) + half * 64;

    int ncc = Kh >> 6;
    int nch = 3 * ncc;

    // per-lane ldmatrix base offsets (within tile, before SW128)
    int a_row_l = wm * 32 + (lane & 15);
    int a_kb_l  = (lane >> 4) * 16;
    int b_row_l = wn * 64 + (lane & 7) + ((lane >> 4) << 3);
    int b_kb_l  = ((lane >> 3) & 1) * 16;

    float acc[2][8][4];
    #pragma unroll
    for (int i = 0; i < 2; i++)
        #pragma unroll
        for (int j = 0; j < 8; j++)
            #pragma unroll
            for (int q = 0; q < 4; q++) acc[i][j][q] = 0.f;

    uint4 ra[4], rb[4];
    // ---- prologue: load chunk 0 ----
    {
        if (arow_ok) {
            const uint4* p = (const uint4*)arow;
            ra[0] = p[0]; ra[1] = p[1]; ra[2] = p[2]; ra[3] = p[3];
        } else ra[0] = ra[1] = ra[2] = ra[3] = make_uint4(0, 0, 0, 0);
        const uint4* q = (const uint4*)brow;
        rb[0] = q[0]; rb[1] = q[1]; rb[2] = q[2]; rb[3] = q[3];
        char* abase = smem;
        char* bbase = smem + 16384;
        #pragma unroll
        for (int u = 0; u < 4; u++) {
            *(uint4*)(abase + SW128(bo + u * 16)) = ra[u];
            *(uint4*)(bbase + SW128(bo + u * 16)) = rb[u];
        }
    }
    __syncthreads();

    for (int c = 0; c < nch; c++) {
        int st = c & 1;
        bool more = (c + 1 < nch);
        // issue global loads for next chunk (overlap with mma below)
        if (more) {
            int cn = c + 1;
            int seg = cn / ncc;
            int cc  = cn - seg * ncc;
            int aoff = ((seg == 2) ? Kh : 0) + (cc << 6);
            int boff = ((seg == 1) ? Kh : 0) + (cc << 6);
            if (arow_ok) {
                const uint4* p = (const uint4*)(arow + (size_t)aoff * 2);
                ra[0] = p[0]; ra[1] = p[1]; ra[2] = p[2]; ra[3] = p[3];
            } else ra[0] = ra[1] = ra[2] = ra[3] = make_uint4(0, 0, 0, 0);
            const uint4* q = (const uint4*)(brow + (size_t)boff * 2);
            rb[0] = q[0]; rb[1] = q[1]; rb[2] = q[2]; rb[3] = q[3];
        }

        uint32_t au = sb + st * HG_STAGE;
        uint32_t bu = au + 16384;
        #pragma unroll
        for (int s = 0; s < 4; s++) {
            uint32_t af[2][4], bf[4][4];
            #pragma unroll
            for (int mf = 0; mf < 2; mf++)
                ldsm4(af[mf], au + SW128((a_row_l + mf * 16) * 128 + s * 32 + a_kb_l));
            #pragma unroll
            for (int np = 0; np < 4; np++)
                ldsm4(bf[np], bu + SW128((b_row_l + np * 16) * 128 + s * 32 + b_kb_l));
            #pragma unroll
            for (int mf = 0; mf < 2; mf++)
                #pragma unroll
                for (int np = 0; np < 4; np++) {
                    mma16816(acc[mf][np * 2 + 0], af[mf][0], af[mf][1], af[mf][2], af[mf][3],
                             bf[np][0], bf[np][1]);
                    mma16816(acc[mf][np * 2 + 1], af[mf][0], af[mf][1], af[mf][2], af[mf][3],
                             bf[np][2], bf[np][3]);
                }
        }

        if (more) {
            char* abase = smem + (st ^ 1) * HG_STAGE;
            char* bbase = abase + 16384;
            #pragma unroll
            for (int u = 0; u < 4; u++) {
                *(uint4*)(abase + SW128(bo + u * 16)) = ra[u];
                *(uint4*)(bbase + SW128(bo + u * 16)) = rb[u];
            }
        }
        __syncthreads();
    }

    // ---- epilogue ----
    int er0 = m0 + wm * 32 + (lane >> 2);
    int ec0 = n0 + wn * 64 + (lane & 3) * 2;
    #pragma unroll
    for (int mf = 0; mf < 2; mf++) {
        #pragma unroll
        for (int nf = 0; nf < 8; nf++) {
            int col = ec0 + nf * 8;
            #pragma unroll
            for (int hrow = 0; hrow < 2; hrow++) {
                int row = er0 + mf * 16 + hrow * 8;
                if (row >= M) continue;
                float v0 = acc[mf][nf][hrow * 2 + 0];
                float v1 = acc[mf][nf][hrow * 2 + 1];
                if (EPI >= 1) {
                    float2 bb = *(const float2*)&bias[col];
                    v0 += bb.x; v1 += bb.y;
                }
                if (EPI == 2) { v0 = gelu_exact(v0); v1 = gelu_exact(v1); }
                size_t o = (size_t)row * N + col;
                if (EPI == 1) {
                    float2 rr = *(const float2*)&res[o];
                    v0 += rr.x; v1 += rr.y;
                }
                float2 w; w.x = v0; w.y = v1;
                *(float2*)&C[o] = w;
            }
        }
    }
}

// ---------------- patch -> kernel attention ----------------
#define PAD 65
__global__ void k_attn_patch(const float* __restrict__ rd,
                             const float* __restrict__ mask, const float* __restrict__ kmask,
                             float inv_denom) {
    extern __shared__ float sm[];
    float* Ks = sm;                    // 144*65
    float* Qs = Ks + KTOK * PAD;       // 32*65
    float* Sc = Qs + 32 * PAD;         // 32*144
    int b = blockIdx.z, h = blockIdx.y;
    int i0 = blockIdx.x * 32;
    int tid = threadIdx.x;
    const float* qkv = d_qkvb;

    for (int idx = tid; idx < KTOK * DH; idx += 256) {
        int j = idx >> 6, d = idx & 63;
        Ks[j * PAD + d] = qkv[(size_t)(KROW0 + b * KTOK + j) * QKVW + DIMM + h * DH + d];
    }
    for (int idx = tid; idx < 32 * DH; idx += 256) {
        int i = idx >> 6, d = idx & 63;
        Qs[i * PAD + d] = qkv[(size_t)(b * NTOK + i0 + i) * QKVW + h * DH + d];
    }
    __syncthreads();

    int warp = tid >> 5, lane = tid & 31;
    #pragma unroll
    for (int qi = 0; qi < 4; qi++) {
        int i = warp * 4 + qi;
        float mi = mask[b * NTOK + i0 + i];
        for (int j = lane; j < KTOK; j += 32) {
            float dot = 0.f;
            #pragma unroll
            for (int d = 0; d < DH; d++) dot += Qs[i * PAD + d] * Ks[j * PAD + d];
            float s = (mi * kmask[b * KTOK + j] < 0.5f) ? NEGBIG : dot * ATT_SCALE;
            Sc[i * KTOK + j] = s;
        }
        float m = -INFINITY;
        for (int j = lane; j < KTOK; j += 32) m = fmaxf(m, Sc[i * KTOK + j]);
        #pragma unroll
        for (int o = 16; o; o >>= 1) m = fmaxf(m, __shfl_xor_sync(0xffffffffu, m, o));
        float ssum = 0.f;
        for (int j = lane; j < KTOK; j += 32) {
            float e = expf(Sc[i * KTOK + j] - m);
            Sc[i * KTOK + j] = e;
            ssum += e;
        }
        #pragma unroll
        for (int o = 16; o; o >>= 1) ssum += __shfl_xor_sync(0xffffffffu, ssum, o);
        float invs = 1.0f / ssum;
        for (int j = lane; j < KTOK; j += 32) {
            float r = rd[(size_t)b * KTOK * NTOK + (size_t)j * NTOK + i0 + i];
            Sc[i * KTOK + j] *= invs * expf(-r * r * inv_denom);
        }
    }
    __syncthreads();

    for (int idx = tid; idx < KTOK * DH; idx += 256) {
        int j = idx >> 6, d = idx & 63;
        Ks[j * PAD + d] = qkv[(size_t)(KROW0 + b * KTOK + j) * QKVW + 2 * DIMM + h * DH + d];
    }
    __syncthreads();

    int i = tid >> 3;
    int d0 = (tid & 7) * 8;
    float acc[8] = {0.f,0.f,0.f,0.f,0.f,0.f,0.f,0.f};
    for (int j = 0; j < KTOK; j++) {
        float p = Sc[i * KTOK + j];
        #pragma unroll
        for (int dd = 0; dd < 8; dd++) acc[dd] += p * Ks[j * PAD + d0 + dd];
    }
    size_t row = (size_t)(b * NTOK + i0 + i);
    #pragma unroll
    for (int dd = 0; dd < 8; dd++)
        d_att[row * DIMM + h * DH + d0 + dd] = acc[dd];
}

// ---------------- kernel -> patch attention ----------------
__global__ __launch_bounds__(256)
void k_attn_kside(const float* __restrict__ rd,
                  const float* __restrict__ mask, const float* __restrict__ kmask,
                  float inv_denom) {
    __shared__ float Sc[NTOK];
    __shared__ float Qs[DH];
    __shared__ float accs[DH];
    int ik = blockIdx.x, h = blockIdx.y, b = blockIdx.z;
    int tid = threadIdx.x;
    const float* qkv = d_qkvb;
    size_t qrow = (size_t)(KROW0 + b * KTOK + ik);

    if (tid < DH) {
        Qs[tid] = qkv[qrow * QKVW + h * DH + tid];
        accs[tid] = 0.f;
    }
    __syncthreads();

    float kmi = kmask[b * KTOK + ik];
    float lmax = -INFINITY;
    for (int j = tid; j < NTOK; j += 256) {
        const float4* kp = (const float4*)&qkv[(size_t)(b * NTOK + j) * QKVW + DIMM + h * DH];
        float dot = 0.f;
        #pragma unroll
        for (int d4 = 0; d4 < 16; d4++) {
            float4 kv = kp[d4];
            dot += Qs[d4*4+0]*kv.x + Qs[d4*4+1]*kv.y + Qs[d4*4+2]*kv.z + Qs[d4*4+3]*kv.w;
        }
        float s = (mask[b * NTOK + j] * kmi < 0.5f) ? NEGBIG : dot * ATT_SCALE;
        Sc[j] = s;
        lmax = fmaxf(lmax, s);
    }
    float M = blockReduceMax256(lmax);
    float lsum = 0.f;
    for (int j = tid; j < NTOK; j += 256) {
        float e = expf(Sc[j] - M);
        Sc[j] = e;
        lsum += e;
    }
    float S = blockReduceSum256(lsum);
    float invS = 1.0f / S;

    float acc[DH];
    #pragma unroll
    for (int d = 0; d < DH; d++) acc[d] = 0.f;
    const float* rdp = rd + (size_t)b * KTOK * NTOK + (size_t)ik * NTOK;
    for (int j = tid; j < NTOK; j += 256) {
        float r = rdp[j];
        float p = Sc[j] * invS * expf(-r * r * inv_denom);
        const float4* vp = (const float4*)&qkv[(size_t)(b * NTOK + j) * QKVW + 2 * DIMM + h * DH];
        #pragma unroll
        for (int d4 = 0; d4 < 16; d4++) {
            float4 vv = vp[d4];
            acc[d4*4+0] += p * vv.x;
            acc[d4*4+1] += p * vv.y;
            acc[d4*4+2] += p * vv.z;
            acc[d4*4+3] += p * vv.w;
        }
    }
    int lane = tid & 31;
    #pragma unroll
    for (int d = 0; d < DH; d++) {
        float v = acc[d];
        #pragma unroll
        for (int o = 16; o; o >>= 1) v += __shfl_down_sync(0xffffffffu, v, o);
        if (lane == 0) atomicAdd(&accs[d], v);
    }
    __syncthreads();
    if (tid < DH)
        d_att[qrow * DIMM + h * DH + tid] = accs[tid];
}

// ---------------- clst -> kernel attention (no decay) ----------------
__global__ void k_attn_clst(const float* __restrict__ mask,
                            const float* __restrict__ kmask) {
    __shared__ float Qc[DH];
    __shared__ float Sc[KTOK];
    int h = blockIdx.x, b = blockIdx.y;
    int tid = threadIdx.x;
    const float* qkv = d_qkvb;
    size_t qrow = (size_t)(CROW0 + b);
    if (tid < DH) Qc[tid] = qkv[qrow * QKVW + h * DH + tid];
    __syncthreads();
    float m0 = mask[b * NTOK];
    float s = -INFINITY;
    if (tid < KTOK) {
        const float4* kp = (const float4*)&qkv[(size_t)(KROW0 + b * KTOK + tid) * QKVW + DIMM + h * DH];
        float dot = 0.f;
        #pragma unroll
        for (int d4 = 0; d4 < 16; d4++) {
            float4 kv = kp[d4];
            dot += Qc[d4*4+0]*kv.x + Qc[d4*4+1]*kv.y + Qc[d4*4+2]*kv.z + Qc[d4*4+3]*kv.w;
        }
        s = (m0 * kmask[b * KTOK + tid] < 0.5f) ? NEGBIG : dot * ATT_SCALE;
        Sc[tid] = s;
    }
    float M = blockReduceMax256(s);
    float e = 0.f;
    if (tid < KTOK) {
        e = expf(s - M);
        Sc[tid] = e;
    }
    float S = blockReduceSum256(e);
    float invS = 1.0f / S;
    if (tid < DH) {
        float a = 0.f;
        for (int j = 0; j < KTOK; j++)
            a += Sc[j] * qkv[(size_t)(KROW0 + b * KTOK + j) * QKVW + 2 * DIMM + h * DH + tid];
        d_att[qrow * DIMM + h * DH + tid] = a * invS;
    }
}

// ---------------- output writes ----------------
__global__ void k_write_krep(float* __restrict__ out, const float* __restrict__ kmask) {
    int idx = blockIdx.x * blockDim.x + threadIdx.x;
    if (idx >= BB * KTOK * DIMM) return;
    int d = idx & 511;
    int row = idx >> 9;
    float km = kmask[row];
    float v = (km < 0.5f) ? 0.f : d_cur[(size_t)(KROW0 + row) * DIMM + d];
    out[idx] = v;
}

__global__ void k_write_clst(float* __restrict__ out) {
    int idx = blockIdx.x * blockDim.x + threadIdx.x;
    if (idx >= BB * DIMM) return;
    int b = idx >> 9, d = idx & 511;
    out[idx] = d_cur[(size_t)(CROW0 + b) * DIMM + d];
}

// ---------------- launcher ----------------
extern "C" void kernel_launch(void* const* d_in, const int* in_sizes, int n_in,
                              void* d_out, int out_size) {
    const float* x     = (const float*)d_in[0];
    const float* kx    = (const float*)d_in[1];
    const float* rd    = (const float*)d_in[2];
    const float* clst  = (const float*)d_in[3];
    const float* mask  = (const float*)d_in[4];
    const float* kmask = (const float*)d_in[5];
    const float* ln1_g = (const float*)d_in[6];
    const float* ln1_b = (const float*)d_in[7];
    const float* w_qkv = (const float*)d_in[8];
    const float* w_out = (const float*)d_in[9];
    const float* b_out = (const float*)d_in[10];
    const float* ln2_g = (const float*)d_in[11];
    const float* ln2_b = (const float*)d_in[12];
    const float* w1    = (const float*)d_in[13];
    const float* b1    = (const float*)d_in[14];
    const float* w2    = (const float*)d_in[15];
    const float* b2    = (const float*)d_in[16];
    float* out = (float*)d_out;

    static float *cur = nullptr, *lnb = nullptr, *qkvb = nullptr, *att = nullptr, *ff = nullptr;
    static __nv_bfloat16 *act2 = nullptr, *wqkv2 = nullptr, *wout2 = nullptr, *w12 = nullptr, *w22 = nullptr;
    if (!cur) {
        cudaGetSymbolAddress((void**)&cur,   d_cur);
        cudaGetSymbolAddress((void**)&lnb,   d_lnb);
        cudaGetSymbolAddress((void**)&qkvb,  d_qkvb);
        cudaGetSymbolAddress((void**)&att,   d_att);
        cudaGetSymbolAddress((void**)&ff,    d_ff);
        cudaGetSymbolAddress((void**)&act2,  d_act2);
        cudaGetSymbolAddress((void**)&wqkv2, d_wqkv2);
        cudaGetSymbolAddress((void**)&wout2, d_wout2);
        cudaGetSymbolAddress((void**)&w12,   d_w12);
        cudaGetSymbolAddress((void**)&w22,   d_w22);
        int patch_smem = (KTOK * PAD + 32 * PAD + 32 * KTOK) * (int)sizeof(float);
        cudaFuncSetAttribute(k_attn_patch, cudaFuncAttributeMaxDynamicSharedMemorySize, patch_smem);
        cudaFuncSetAttribute(k_hgemm<0>, cudaFuncAttributeMaxDynamicSharedMemorySize, HG_SMEM);
        cudaFuncSetAttribute(k_hgemm<1>, cudaFuncAttributeMaxDynamicSharedMemorySize, HG_SMEM);
        cudaFuncSetAttribute(k_hgemm<2>, cudaFuncAttributeMaxDynamicSharedMemorySize, HG_SMEM);
    }
    int patch_smem = (KTOK * PAD + 32 * PAD + 32 * KTOK) * (int)sizeof(float);

    int mtiles = (RTOT + 127) / 128;  // 67
    dim3 wblk(32, 8);

    // weight transpose+split (all layers)
    for (int l = 0; l < DEPTHL; l++) {
        k_wsplit<<<dim3(QKVW / 32, DIMM / 32), wblk>>>(w_qkv + (size_t)l * DIMM * QKVW,
                wqkv2 + (size_t)l * QKVW * 2 * DIMM, DIMM, QKVW);
        k_wsplit<<<dim3(DIMM / 32, DIMM / 32), wblk>>>(w_out + (size_t)l * DIMM * DIMM,
                wout2 + (size_t)l * DIMM * 2 * DIMM, DIMM, DIMM);
        k_wsplit<<<dim3(MLPW / 32, DIMM / 32), wblk>>>(w1 + (size_t)l * DIMM * MLPW,
                w12 + (size_t)l * MLPW * 2 * DIMM, DIMM, MLPW);
        k_wsplit<<<dim3(DIMM / 32, MLPW / 32), wblk>>>(w2 + (size_t)l * MLPW * DIMM,
                w22 + (size_t)l * DIMM * 2 * MLPW, MLPW, DIMM);
    }

    k_init<<<(RTOT * DIMM + 255) / 256, 256>>>(x, kx, clst);

    for (int l = 0; l < DEPTHL; l++) {
        float inv_denom = 1.0f / (64.0f * (float)(1 << l));

        // LN1 (destructive)
        k_layernorm<0><<<RTOT, 256>>>(ln1_g + l * DIMM, ln1_b + l * DIMM);

        // QKV projection
        k_asplit<DIMM><<<(RTOT * DIMM + 255) / 256, 256>>>(cur, act2);
        k_hgemm<0><<<dim3(QKVW / 128, mtiles), 256, HG_SMEM>>>(RTOT, QKVW, DIMM,
                act2, wqkv2 + (size_t)l * QKVW * 2 * DIMM, nullptr, nullptr, qkvb);

        // attentions
        k_attn_patch<<<dim3(NTOK / 32, NHEAD, BB), 256, patch_smem>>>(rd, mask, kmask, inv_denom);
        k_attn_kside<<<dim3(KTOK, NHEAD, BB), 256>>>(rd, mask, kmask, inv_denom);
        k_attn_clst<<<dim3(NHEAD, BB), 256>>>(mask, kmask);

        // out projection + residual
        k_asplit<DIMM><<<(RTOT * DIMM + 255) / 256, 256>>>(att, act2);
        k_hgemm<1><<<dim3(DIMM / 128, mtiles), 256, HG_SMEM>>>(RTOT, DIMM, DIMM,
                act2, wout2 + (size_t)l * DIMM * 2 * DIMM, b_out + l * DIMM, cur, cur);

        // FFN
        k_layernorm<1><<<RTOT, 256>>>(ln2_g + l * DIMM, ln2_b + l * DIMM);
        k_asplit<DIMM><<<(RTOT * DIMM + 255) / 256, 256>>>(lnb, act2);
        k_hgemm<2><<<dim3(MLPW / 128, mtiles), 256, HG_SMEM>>>(RTOT, MLPW, DIMM,
                act2, w12 + (size_t)l * MLPW * 2 * DIMM, b1 + l * MLPW, nullptr, ff);
        k_asplit<MLPW><<<(RTOT * MLPW + 255) / 256, 256>>>(ff, act2);
        k_hgemm<1><<<dim3(DIMM / 128, mtiles), 256, HG_SMEM>>>(RTOT, DIMM, MLPW,
                act2, w22 + (size_t)l * DIMM * 2 * MLPW, b2 + l * DIMM, cur, cur);

        k_write_krep<<<(BB * KTOK * DIMM + 255) / 256, 256>>>(
                out + (size_t)l * BB * KTOK * DIMM, kmask);
    }

    k_write_clst<<<(BB * DIMM + 255) / 256, 256>>>(out + (size_t)DEPTHL * BB * KTOK * DIMM);
}

// round 7
// speedup vs baseline: 2.1060x; 1.7074x over previous
#include <cuda_runtime.h>
#include <cuda_bf16.h>
#include <math.h>
#include <stdint.h>

// ---------------- problem constants ----------------
#define BB    2
#define NTOK  4096
#define KTOK  144
#define DIMM  512
#define NHEAD 8
#define DH    64
#define QKVW  1536
#define MLPW  2048
#define DEPTHL 4
#define RTOT  (BB*NTOK + BB*KTOK + BB)   // 8482
#define KROW0 (BB*NTOK)                  // 8192
#define CROW0 (BB*NTOK + BB*KTOK)        // 8480
#define NEGBIG (-1e9f)
#define ATT_SCALE 0.125f                 // 64^-0.5

// ---------------- scratch (device globals; no malloc allowed) ----------------
__device__ float d_cur[RTOT*DIMM];
__device__ float d_qkvb[RTOT*QKVW];
// split-bf16 operands (hi | lo halves along K)
__device__ __align__(128) __nv_bfloat16 d_act2[RTOT*2*DIMM];          // [RTOT, 1024]
__device__ __align__(128) __nv_bfloat16 d_ff2[RTOT*2*MLPW];           // [RTOT, 4096]
__device__ __align__(128) __nv_bfloat16 d_wqkv2[DEPTHL*QKVW*2*DIMM];
__device__ __align__(128) __nv_bfloat16 d_wout2[DEPTHL*DIMM*2*DIMM];
__device__ __align__(128) __nv_bfloat16 d_w12[DEPTHL*MLPW*2*DIMM];
__device__ __align__(128) __nv_bfloat16 d_w22[DEPTHL*DIMM*2*MLPW];

// ---------------- helpers ----------------
__device__ __forceinline__ uint32_t smem_u32(const void* p) {
    uint32_t a;
    asm("{ .reg .u64 t; cvta.to.shared.u64 t, %1; cvt.u32.u64 %0, t; }" : "=r"(a) : "l"(p));
    return a;
}
#define SW128(x) ((x) ^ (((x) >> 3) & 0x70))

__device__ __forceinline__ void ldsm4(uint32_t* r, uint32_t addr) {
    asm volatile("ldmatrix.sync.aligned.m8n8.x4.shared.b16 {%0,%1,%2,%3}, [%4];"
        : "=r"(r[0]), "=r"(r[1]), "=r"(r[2]), "=r"(r[3]) : "r"(addr));
}
__device__ __forceinline__ void mma16816(float* c,
        uint32_t a0, uint32_t a1, uint32_t a2, uint32_t a3,
        uint32_t b0, uint32_t b1) {
    asm volatile("mma.sync.aligned.m16n8k16.row.col.f32.bf16.bf16.f32 "
        "{%0,%1,%2,%3}, {%4,%5,%6,%7}, {%8,%9}, {%0,%1,%2,%3};"
        : "+f"(c[0]), "+f"(c[1]), "+f"(c[2]), "+f"(c[3])
        : "r"(a0), "r"(a1), "r"(a2), "r"(a3), "r"(b0), "r"(b1));
}
__device__ __forceinline__ void cpasync16(uint32_t dst, const void* src, int srcsize) {
    asm volatile("cp.async.cg.shared.global [%0], [%1], 16, %2;"
        :: "r"(dst), "l"(src), "r"(srcsize) : "memory");
}
#define CP_COMMIT() asm volatile("cp.async.commit_group;" ::: "memory")
#define CP_WAIT1()  asm volatile("cp.async.wait_group 1;" ::: "memory")

__device__ __forceinline__ float gelu_exact(float v) {
    return 0.5f * v * (1.0f + erff(v * 0.70710678118654752f));
}
__device__ __forceinline__ void split_store_pair(__nv_bfloat16* base, size_t hi_idx,
                                                 int lo_off, float v0, float v1) {
    __nv_bfloat162 h, l;
    h.x = __float2bfloat16(v0);
    h.y = __float2bfloat16(v1);
    l.x = __float2bfloat16(v0 - __bfloat162float(h.x));
    l.y = __float2bfloat16(v1 - __bfloat162float(h.y));
    *(__nv_bfloat162*)&base[hi_idx] = h;
    *(__nv_bfloat162*)&base[hi_idx + lo_off] = l;
}

// ---------------- reduction helpers (256-thread blocks) ----------------
__device__ __forceinline__ float blockReduceSum256(float v) {
    __shared__ float sh[8];
    int lane = threadIdx.x & 31, w = threadIdx.x >> 5;
    #pragma unroll
    for (int o = 16; o; o >>= 1) v += __shfl_down_sync(0xffffffffu, v, o);
    if (lane == 0) sh[w] = v;
    __syncthreads();
    float r;
    if (threadIdx.x < 8) r = sh[threadIdx.x]; else r = 0.f;
    if (w == 0) {
        #pragma unroll
        for (int o = 4; o; o >>= 1) r += __shfl_down_sync(0xffu, r, o);
        if (lane == 0) sh[0] = r;
    }
    __syncthreads();
    r = sh[0];
    __syncthreads();
    return r;
}
__device__ __forceinline__ float blockReduceMax256(float v) {
    __shared__ float sh[8];
    int lane = threadIdx.x & 31, w = threadIdx.x >> 5;
    #pragma unroll
    for (int o = 16; o; o >>= 1) v = fmaxf(v, __shfl_down_sync(0xffffffffu, v, o));
    if (lane == 0) sh[w] = v;
    __syncthreads();
    float r;
    if (threadIdx.x < 8) r = sh[threadIdx.x]; else r = -INFINITY;
    if (w == 0) {
        #pragma unroll
        for (int o = 4; o; o >>= 1) r = fmaxf(r, __shfl_down_sync(0xffu, r, o));
        if (lane == 0) sh[0] = r;
    }
    __syncthreads();
    r = sh[0];
    __syncthreads();
    return r;
}

// ---------------- init ----------------
__global__ void k_init(const float* __restrict__ x, const float* __restrict__ kx,
                       const float* __restrict__ clst) {
    int idx = blockIdx.x * blockDim.x + threadIdx.x;
    if (idx >= RTOT * DIMM) return;
    int row = idx >> 9;
    int d   = idx & 511;
    float v;
    if (row < KROW0)        v = x[idx];
    else if (row < CROW0)   v = kx[(row - KROW0) * DIMM + d];
    else                    v = clst[(row - CROW0) * DIMM + d];
    d_cur[idx] = v;
}

// ---------------- LayerNorm (fused split emission) ----------------
// MODE 0: out -> d_cur (fp32, destructive) AND d_act2 (split bf16)
// MODE 1: out -> d_act2 only (split bf16)
template<int MODE>
__global__ void k_layernorm(const float* __restrict__ g, const float* __restrict__ bp) {
    int row = blockIdx.x;
    int t = threadIdx.x;
    const float* r = d_cur + (size_t)row * DIMM;
    float v0 = r[t];
    float v1 = r[t + 256];
    float s  = blockReduceSum256(v0 + v1);
    float mean = s * (1.0f / DIMM);
    float d0 = v0 - mean, d1 = v1 - mean;
    float sq = blockReduceSum256(d0 * d0 + d1 * d1);
    float inv = rsqrtf(sq * (1.0f / DIMM) + 1e-5f);
    float o0 = d0 * inv * g[t]       + bp[t];
    float o1 = d1 * inv * g[t + 256] + bp[t + 256];
    if (MODE == 0) {
        float* o = d_cur + (size_t)row * DIMM;
        o[t] = o0;
        o[t + 256] = o1;
    }
    size_t base = (size_t)row * (2 * DIMM);
    __nv_bfloat16 h0 = __float2bfloat16(o0);
    __nv_bfloat16 h1 = __float2bfloat16(o1);
    d_act2[base + t]              = h0;
    d_act2[base + t + 256]        = h1;
    d_act2[base + DIMM + t]       = __float2bfloat16(o0 - __bfloat162float(h0));
    d_act2[base + DIMM + t + 256] = __float2bfloat16(o1 - __bfloat162float(h1));
}

// ---------------- weight transpose + split ----------------
__global__ void k_wsplit(const float* __restrict__ W, __nv_bfloat16* __restrict__ WT,
                         int K, int N) {
    __shared__ float t[32][33];
    int k0 = blockIdx.y * 32, n0 = blockIdx.x * 32;
    int tx = threadIdx.x, ty = threadIdx.y;      // block (32,8)
    #pragma unroll
    for (int i = 0; i < 32; i += 8)
        t[ty + i][tx] = W[(size_t)(k0 + ty + i) * N + n0 + tx];
    __syncthreads();
    #pragma unroll
    for (int i = 0; i < 32; i += 8) {
        int n = n0 + ty + i, k = k0 + tx;
        float v = t[tx][ty + i];
        __nv_bfloat16 hi = __float2bfloat16(v);
        float lo = v - __bfloat162float(hi);
        WT[(size_t)n * (2 * K) + k]     = hi;
        WT[(size_t)n * (2 * K) + K + k] = __float2bfloat16(lo);
    }
}

// ---------------- HMMA bf16x3 GEMM (256x128 tile, cp.async 3-stage) ----------------
// C[M,N] = A[M,Kh]*B^T, split operands A2 [M,2Kh], B2 [N,2Kh] (bf16 hi|lo).
// Virtual K segments: (hiA,hiB), (hiA,loB), (loA,hiB).
// CTA 256x128, 8 warps (4M x 2N), warp tile 64x64, K-chunk 64.
// EPI 0: plain f32   EPI 1: +bias,+residual f32   EPI 2: +bias, GELU, SPLIT-bf16 out
#define HBM 256
#define HABYTES (HBM*128)        // 32768
#define HBBYTES (128*128)        // 16384
#define HSTAGEB (HABYTES+HBBYTES)
#define HG_SMEM (3*HSTAGEB)      // 147456

template<int EPI>
__global__ __launch_bounds__(256, 1)
void k_hgemm(int M, int N, int Kh,
             const __nv_bfloat16* __restrict__ A2, const __nv_bfloat16* __restrict__ B2,
             const float* __restrict__ bias, const float* __restrict__ res,
             float* __restrict__ C) {
    extern __shared__ char smem[];
    uint32_t sb = smem_u32(smem);
    int tid = threadIdx.x, wid = tid >> 5, lane = tid & 31;
    int m0 = blockIdx.y * HBM, n0 = blockIdx.x * 128;
    int K2 = 2 * Kh;
    int wm = wid & 3, wn = wid >> 2;   // warp tile 64M x 64N

    int ncc = Kh >> 6;
    int nch = 3 * ncc;

    // global->smem mapping: A row = tid (8x16B); B row = tid>>1, half tid&1 (4x16B)
    int arow_g = m0 + tid;
    int asz = (arow_g < M) ? 16 : 0;
    const char* arow = (const char*)(A2 + (size_t)((arow_g < M) ? arow_g : (M - 1)) * K2);
    int brw = tid >> 1, bh = tid & 1;
    const char* brow = (const char*)(B2 + (size_t)(n0 + brw) * K2) + bh * 64;

    auto load_chunk = [&](int stg, int c) {
        int seg = c / ncc;
        int cc  = c - seg * ncc;
        int aoff = ((seg == 2) ? Kh : 0) + (cc << 6);
        int boff = ((seg == 1) ? Kh : 0) + (cc << 6);
        uint32_t abase = sb + stg * HSTAGEB;
        uint32_t bbase = abase + HABYTES;
        const char* asrc = arow + (size_t)aoff * 2;
        #pragma unroll
        for (int u = 0; u < 8; u++)
            cpasync16(abase + SW128(tid * 128 + u * 16), asrc + u * 16, asz);
        const char* bsrc = brow + (size_t)boff * 2;
        #pragma unroll
        for (int u = 0; u < 4; u++)
            cpasync16(bbase + SW128(brw * 128 + bh * 64 + u * 16), bsrc + u * 16, 16);
    };

    float acc[4][8][4];
    #pragma unroll
    for (int i = 0; i < 4; i++)
        #pragma unroll
        for (int j = 0; j < 8; j++)
            #pragma unroll
            for (int q = 0; q < 4; q++) acc[i][j][q] = 0.f;

    load_chunk(0, 0); CP_COMMIT();
    load_chunk(1, 1); CP_COMMIT();

    int a_row_l = wm * 64 + (lane & 15);
    int a_kb_l  = (lane >> 4) * 16;
    int b_row_l = wn * 64 + (lane & 7) + ((lane >> 4) << 3);
    int b_kb_l  = ((lane >> 3) & 1) * 16;

    for (int c = 0; c < nch; c++) {
        CP_WAIT1();
        __syncthreads();
        uint32_t au = sb + (c % 3) * HSTAGEB;
        uint32_t bu = au + HABYTES;
        #pragma unroll
        for (int s = 0; s < 4; s++) {
            uint32_t af[4][4], bf[4][4];
            #pragma unroll
            for (int mf = 0; mf < 4; mf++)
                ldsm4(af[mf], au + SW128((a_row_l + mf * 16) * 128 + s * 32 + a_kb_l));
            #pragma unroll
            for (int np = 0; np < 4; np++)
                ldsm4(bf[np], bu + SW128((b_row_l + np * 16) * 128 + s * 32 + b_kb_l));
            #pragma unroll
            for (int mf = 0; mf < 4; mf++)
                #pragma unroll
                for (int np = 0; np < 4; np++) {
                    mma16816(acc[mf][np * 2 + 0], af[mf][0], af[mf][1], af[mf][2], af[mf][3],
                             bf[np][0], bf[np][1]);
                    mma16816(acc[mf][np * 2 + 1], af[mf][0], af[mf][1], af[mf][2], af[mf][3],
                             bf[np][2], bf[np][3]);
                }
        }
        int cn = c + 2;
        if (cn < nch) { load_chunk(cn % 3, cn); CP_COMMIT(); }
    }

    // ---- epilogue ----
    #pragma unroll
    for (int mf = 0; mf < 4; mf++) {
        #pragma unroll
        for (int nf = 0; nf < 8; nf++) {
            int col = n0 + wn * 64 + nf * 8 + (lane & 3) * 2;
            #pragma unroll
            for (int hrow = 0; hrow < 2; hrow++) {
                int row = m0 + wm * 64 + mf * 16 + hrow * 8 + (lane >> 2);
                if (row >= M) continue;
                float v0 = acc[mf][nf][hrow * 2 + 0];
                float v1 = acc[mf][nf][hrow * 2 + 1];
                if (EPI >= 1) {
                    float2 bb = *(const float2*)&bias[col];
                    v0 += bb.x; v1 += bb.y;
                }
                if (EPI == 2) {
                    v0 = gelu_exact(v0); v1 = gelu_exact(v1);
                    split_store_pair((__nv_bfloat16*)C, (size_t)row * (2 * N) + col, N, v0, v1);
                } else {
                    size_t o = (size_t)row * N + col;
                    if (EPI == 1) {
                        float2 rr = *(const float2*)&res[o];
                        v0 += rr.x; v1 += rr.y;
                    }
                    float2 w; w.x = v0; w.y = v1;
                    *(float2*)&C[o] = w;
                }
            }
        }
    }
}

// ---------------- patch -> kernel attention (float4 LDS, split output) ----------------
#define PAD 68
__global__ void k_attn_patch(const float* __restrict__ rd,
                             const float* __restrict__ mask, const float* __restrict__ kmask,
                             float inv_denom) {
    extern __shared__ float sm[];
    float* Ks = sm;                    // 144*68
    float* Qs = Ks + KTOK * PAD;       // 32*68
    float* Sc = Qs + 32 * PAD;         // 32*144
    int b = blockIdx.z, h = blockIdx.y;
    int i0 = blockIdx.x * 32;
    int tid = threadIdx.x;
    const float* qkv = d_qkvb;

    // stage K (float4)
    for (int idx = tid; idx < KTOK * 16; idx += 256) {
        int j = idx >> 4, d = (idx & 15) * 4;
        *(float4*)&Ks[j * PAD + d] =
            *(const float4*)&qkv[(size_t)(KROW0 + b * KTOK + j) * QKVW + DIMM + h * DH + d];
    }
    for (int idx = tid; idx < 32 * 16; idx += 256) {
        int i = idx >> 4, d = (idx & 15) * 4;
        *(float4*)&Qs[i * PAD + d] =
            *(const float4*)&qkv[(size_t)(b * NTOK + i0 + i) * QKVW + h * DH + d];
    }
    __syncthreads();

    int warp = tid >> 5, lane = tid & 31;
    #pragma unroll
    for (int qi = 0; qi < 4; qi++) {
        int i = warp * 4 + qi;
        float mi = mask[b * NTOK + i0 + i];
        for (int j = lane; j < KTOK; j += 32) {
            float dot = 0.f;
            #pragma unroll
            for (int d = 0; d < DH; d += 4) {
                float4 q = *(float4*)&Qs[i * PAD + d];
                float4 k = *(float4*)&Ks[j * PAD + d];
                dot += q.x * k.x + q.y * k.y + q.z * k.z + q.w * k.w;
            }
            float s = (mi * kmask[b * KTOK + j] < 0.5f) ? NEGBIG : dot * ATT_SCALE;
            Sc[i * KTOK + j] = s;
        }
        float m = -INFINITY;
        for (int j = lane; j < KTOK; j += 32) m = fmaxf(m, Sc[i * KTOK + j]);
        #pragma unroll
        for (int o = 16; o; o >>= 1) m = fmaxf(m, __shfl_xor_sync(0xffffffffu, m, o));
        float ssum = 0.f;
        for (int j = lane; j < KTOK; j += 32) {
            float e = expf(Sc[i * KTOK + j] - m);
            Sc[i * KTOK + j] = e;
            ssum += e;
        }
        #pragma unroll
        for (int o = 16; o; o >>= 1) ssum += __shfl_xor_sync(0xffffffffu, ssum, o);
        float invs = 1.0f / ssum;
        for (int j = lane; j < KTOK; j += 32) {
            float r = rd[(size_t)b * KTOK * NTOK + (size_t)j * NTOK + i0 + i];
            Sc[i * KTOK + j] *= invs * expf(-r * r * inv_denom);
        }
    }
    __syncthreads();

    // stage V over Ks
    for (int idx = tid; idx < KTOK * 16; idx += 256) {
        int j = idx >> 4, d = (idx & 15) * 4;
        *(float4*)&Ks[j * PAD + d] =
            *(const float4*)&qkv[(size_t)(KROW0 + b * KTOK + j) * QKVW + 2 * DIMM + h * DH + d];
    }
    __syncthreads();

    int i = tid >> 3;
    int d0 = (tid & 7) * 8;
    float acc[8] = {0.f,0.f,0.f,0.f,0.f,0.f,0.f,0.f};
    for (int j = 0; j < KTOK; j++) {
        float p = Sc[i * KTOK + j];
        float4 v0 = *(float4*)&Ks[j * PAD + d0];
        float4 v1 = *(float4*)&Ks[j * PAD + d0 + 4];
        acc[0] += p * v0.x; acc[1] += p * v0.y; acc[2] += p * v0.z; acc[3] += p * v0.w;
        acc[4] += p * v1.x; acc[5] += p * v1.y; acc[6] += p * v1.z; acc[7] += p * v1.w;
    }
    size_t row = (size_t)(b * NTOK + i0 + i);
    size_t base = row * (2 * DIMM) + h * DH + d0;
    #pragma unroll
    for (int u = 0; u < 4; u++)
        split_store_pair(d_act2, base + 2 * u, DIMM, acc[2 * u], acc[2 * u + 1]);
}

// ---------------- kernel -> patch attention (flash-style tiles) ----------------
#define FTK 16
#define FTN 64
#define KP  68
__global__ __launch_bounds__(256)
void k_attn_kside(const float* __restrict__ rd,
                  const float* __restrict__ mask, const float* __restrict__ kmask,
                  float inv_denom) {
    __shared__ float Qs[FTK][KP];
    __shared__ float Ks[FTN][KP];
    __shared__ float Vs[FTN][KP];
    __shared__ float Ps[FTK][FTN];
    __shared__ float kmrow[FTK];
    int ik0 = blockIdx.x * FTK, h = blockIdx.y, b = blockIdx.z;
    int tid = threadIdx.x;
    int ik = tid >> 4, sub = tid & 15;
    const float* qkv = d_qkvb;

    {
        int r = tid >> 4, d = (tid & 15) * 4;
        *(float4*)&Qs[r][d] =
            *(const float4*)&qkv[(size_t)(KROW0 + b * KTOK + ik0 + r) * QKVW + h * DH + d];
        if (tid < FTK) kmrow[tid] = kmask[b * KTOK + ik0 + tid];
    }
    __syncthreads();
    float kmi = kmrow[ik];
    const float* rdrow = rd + (size_t)b * KTOK * NTOK + (size_t)(ik0 + ik) * NTOK;

    float m_run = -INFINITY, l_run = 0.f;
    float a0 = 0.f, a1 = 0.f, a2 = 0.f, a3 = 0.f;

    for (int n0 = 0; n0 < NTOK; n0 += FTN) {
        {
            int r = tid >> 2, d = (tid & 3) * 16;
            const float* kp = &qkv[(size_t)(b * NTOK + n0 + r) * QKVW + DIMM + h * DH + d];
            const float* vp = &qkv[(size_t)(b * NTOK + n0 + r) * QKVW + 2 * DIMM + h * DH + d];
            #pragma unroll
            for (int u = 0; u < 4; u++) {
                *(float4*)&Ks[r][d + u * 4] = *(const float4*)(kp + u * 4);
                *(float4*)&Vs[r][d + u * 4] = *(const float4*)(vp + u * 4);
            }
        }
        __syncthreads();

        // phase 1: scores for j = sub + 16*jj
        float s[4] = {0.f, 0.f, 0.f, 0.f};
        #pragma unroll
        for (int d = 0; d < DH; d += 4) {
            float4 q = *(float4*)&Qs[ik][d];
            #pragma unroll
            for (int jj = 0; jj < 4; jj++) {
                float4 k = *(float4*)&Ks[sub + jj * 16][d];
                s[jj] += q.x * k.x + q.y * k.y + q.z * k.z + q.w * k.w;
            }
        }
        float tmax = -INFINITY;
        #pragma unroll
        for (int jj = 0; jj < 4; jj++) {
            int jg = n0 + sub + jj * 16;
            s[jj] = (mask[b * NTOK + jg] * kmi < 0.5f) ? NEGBIG : s[jj] * ATT_SCALE;
            tmax = fmaxf(tmax, s[jj]);
        }
        #pragma unroll
        for (int o = 8; o; o >>= 1)
            tmax = fmaxf(tmax, __shfl_xor_sync(0xffffffffu, tmax, o, 16));
        float m_new = fmaxf(m_run, tmax);
        float scale = expf(m_run - m_new);
        float tsum = 0.f;
        #pragma unroll
        for (int jj = 0; jj < 4; jj++) {
            float e = expf(s[jj] - m_new);
            tsum += e;
            int j = sub + jj * 16;
            float r = rdrow[n0 + j];
            Ps[ik][j] = e * expf(-r * r * inv_denom);
        }
        #pragma unroll
        for (int o = 8; o; o >>= 1)
            tsum += __shfl_xor_sync(0xffffffffu, tsum, o, 16);
        l_run = l_run * scale + tsum;
        m_run = m_new;
        __syncwarp();

        // phase 2: accumulate decayed numerator
        a0 *= scale; a1 *= scale; a2 *= scale; a3 *= scale;
        int d = sub * 4;
        #pragma unroll 8
        for (int j = 0; j < FTN; j++) {
            float p = Ps[ik][j];
            float4 v = *(float4*)&Vs[j][d];
            a0 += p * v.x; a1 += p * v.y; a2 += p * v.z; a3 += p * v.w;
        }
        __syncthreads();
    }

    float invl = 1.0f / l_run;
    size_t row = (size_t)(KROW0 + b * KTOK + ik0 + ik);
    size_t base = row * (2 * DIMM) + h * DH + sub * 4;
    split_store_pair(d_act2, base,     DIMM, a0 * invl, a1 * invl);
    split_store_pair(d_act2, base + 2, DIMM, a2 * invl, a3 * invl);
}

// ---------------- clst -> kernel attention ----------------
__global__ void k_attn_clst(const float* __restrict__ mask,
                            const float* __restrict__ kmask) {
    __shared__ float Qc[DH];
    __shared__ float Sc[KTOK];
    int h = blockIdx.x, b = blockIdx.y;
    int tid = threadIdx.x;
    const float* qkv = d_qkvb;
    size_t qrow = (size_t)(CROW0 + b);
    if (tid < DH) Qc[tid] = qkv[qrow * QKVW + h * DH + tid];
    __syncthreads();
    float m0 = mask[b * NTOK];
    float s = -INFINITY;
    if (tid < KTOK) {
        const float4* kp = (const float4*)&qkv[(size_t)(KROW0 + b * KTOK + tid) * QKVW + DIMM + h * DH];
        float dot = 0.f;
        #pragma unroll
        for (int d4 = 0; d4 < 16; d4++) {
            float4 kv = kp[d4];
            dot += Qc[d4*4+0]*kv.x + Qc[d4*4+1]*kv.y + Qc[d4*4+2]*kv.z + Qc[d4*4+3]*kv.w;
        }
        s = (m0 * kmask[b * KTOK + tid] < 0.5f) ? NEGBIG : dot * ATT_SCALE;
        Sc[tid] = s;
    }
    float M = blockReduceMax256(s);
    float e = 0.f;
    if (tid < KTOK) {
        e = expf(s - M);
        Sc[tid] = e;
    }
    float S = blockReduceSum256(e);
    float invS = 1.0f / S;
    if (tid < DH) {
        float a = 0.f;
        for (int j = 0; j < KTOK; j++)
            a += Sc[j] * qkv[(size_t)(KROW0 + b * KTOK + j) * QKVW + 2 * DIMM + h * DH + tid];
        a *= invS;
        size_t base = qrow * (2 * DIMM) + h * DH + tid;
        __nv_bfloat16 hi = __float2bfloat16(a);
        d_act2[base] = hi;
        d_act2[base + DIMM] = __float2bfloat16(a - __bfloat162float(hi));
    }
}

// ---------------- output writes ----------------
__global__ void k_write_krep(float* __restrict__ out, const float* __restrict__ kmask) {
    int idx = blockIdx.x * blockDim.x + threadIdx.x;
    if (idx >= BB * KTOK * DIMM) return;
    int d = idx & 511;
    int row = idx >> 9;
    float km = kmask[row];
    out[idx] = (km < 0.5f) ? 0.f : d_cur[(size_t)(KROW0 + row) * DIMM + d];
}
__global__ void k_write_clst(float* __restrict__ out) {
    int idx = blockIdx.x * blockDim.x + threadIdx.x;
    if (idx >= BB * DIMM) return;
    int b = idx >> 9, d = idx & 511;
    out[idx] = d_cur[(size_t)(CROW0 + b) * DIMM + d];
}

// ---------------- launcher ----------------
extern "C" void kernel_launch(void* const* d_in, const int* in_sizes, int n_in,
                              void* d_out, int out_size) {
    const float* x     = (const float*)d_in[0];
    const float* kx    = (const float*)d_in[1];
    const float* rd    = (const float*)d_in[2];
    const float* clst  = (const float*)d_in[3];
    const float* mask  = (const float*)d_in[4];
    const float* kmask = (const float*)d_in[5];
    const float* ln1_g = (const float*)d_in[6];
    const float* ln1_b = (const float*)d_in[7];
    const float* w_qkv = (const float*)d_in[8];
    const float* w_out = (const float*)d_in[9];
    const float* b_out = (const float*)d_in[10];
    const float* ln2_g = (const float*)d_in[11];
    const float* ln2_b = (const float*)d_in[12];
    const float* w1    = (const float*)d_in[13];
    const float* b1    = (const float*)d_in[14];
    const float* w2    = (const float*)d_in[15];
    const float* b2    = (const float*)d_in[16];
    float* out = (float*)d_out;

    static float *cur = nullptr, *qkvb = nullptr;
    static __nv_bfloat16 *act2 = nullptr, *ff2 = nullptr;
    static __nv_bfloat16 *wqkv2 = nullptr, *wout2 = nullptr, *w12 = nullptr, *w22 = nullptr;
    if (!cur) {
        cudaGetSymbolAddress((void**)&cur,   d_cur);
        cudaGetSymbolAddress((void**)&qkvb,  d_qkvb);
        cudaGetSymbolAddress((void**)&act2,  d_act2);
        cudaGetSymbolAddress((void**)&ff2,   d_ff2);
        cudaGetSymbolAddress((void**)&wqkv2, d_wqkv2);
        cudaGetSymbolAddress((void**)&wout2, d_wout2);
        cudaGetSymbolAddress((void**)&w12,   d_w12);
        cudaGetSymbolAddress((void**)&w22,   d_w22);
        int patch_smem = (KTOK * PAD + 32 * PAD + 32 * KTOK) * (int)sizeof(float);
        cudaFuncSetAttribute(k_attn_patch, cudaFuncAttributeMaxDynamicSharedMemorySize, patch_smem);
        cudaFuncSetAttribute(k_hgemm<0>, cudaFuncAttributeMaxDynamicSharedMemorySize, HG_SMEM);
        cudaFuncSetAttribute(k_hgemm<1>, cudaFuncAttributeMaxDynamicSharedMemorySize, HG_SMEM);
        cudaFuncSetAttribute(k_hgemm<2>, cudaFuncAttributeMaxDynamicSharedMemorySize, HG_SMEM);
    }
    int patch_smem = (KTOK * PAD + 32 * PAD + 32 * KTOK) * (int)sizeof(float);

    int mt = (RTOT + HBM - 1) / HBM;   // 34
    dim3 wblk(32, 8);

    for (int l = 0; l < DEPTHL; l++) {
        k_wsplit<<<dim3(QKVW / 32, DIMM / 32), wblk>>>(w_qkv + (size_t)l * DIMM * QKVW,
                wqkv2 + (size_t)l * QKVW * 2 * DIMM, DIMM, QKVW);
        k_wsplit<<<dim3(DIMM / 32, DIMM / 32), wblk>>>(w_out + (size_t)l * DIMM * DIMM,
                wout2 + (size_t)l * DIMM * 2 * DIMM, DIMM, DIMM);
        k_wsplit<<<dim3(MLPW / 32, DIMM / 32), wblk>>>(w1 + (size_t)l * DIMM * MLPW,
                w12 + (size_t)l * MLPW * 2 * DIMM, DIMM, MLPW);
        k_wsplit<<<dim3(DIMM / 32, MLPW / 32), wblk>>>(w2 + (size_t)l * MLPW * DIMM,
                w22 + (size_t)l * DIMM * 2 * MLPW, MLPW, DIMM);
    }

    k_init<<<(RTOT * DIMM + 255) / 256, 256>>>(x, kx, clst);

    for (int l = 0; l < DEPTHL; l++) {
        float inv_denom = 1.0f / (64.0f * (float)(1 << l));

        // LN1 (destructive) -> cur fp32 + act2 split
        k_layernorm<0><<<RTOT, 256>>>(ln1_g + l * DIMM, ln1_b + l * DIMM);

        // QKV projection -> qkvb fp32
        k_hgemm<0><<<dim3(QKVW / 128, mt), 256, HG_SMEM>>>(RTOT, QKVW, DIMM,
                act2, wqkv2 + (size_t)l * QKVW * 2 * DIMM, nullptr, nullptr, qkvb);

        // attentions -> act2 split (merged heads)
        k_attn_patch<<<dim3(NTOK / 32, NHEAD, BB), 256, patch_smem>>>(rd, mask, kmask, inv_denom);
        k_attn_kside<<<dim3(KTOK / FTK, NHEAD, BB), 256>>>(rd, mask, kmask, inv_denom);
        k_attn_clst<<<dim3(NHEAD, BB), 256>>>(mask, kmask);

        // out projection + residual -> cur fp32
        k_hgemm<1><<<dim3(DIMM / 128, mt), 256, HG_SMEM>>>(RTOT, DIMM, DIMM,
                act2, wout2 + (size_t)l * DIMM * 2 * DIMM, b_out + l * DIMM, cur, cur);

        // FFN
        k_layernorm<1><<<RTOT, 256>>>(ln2_g + l * DIMM, ln2_b + l * DIMM);
        k_hgemm<2><<<dim3(MLPW / 128, mt), 256, HG_SMEM>>>(RTOT, MLPW, DIMM,
                act2, w12 + (size_t)l * MLPW * 2 * DIMM, b1 + l * MLPW, nullptr, (float*)ff2);
        k_hgemm<1><<<dim3(DIMM / 128, mt), 256, HG_SMEM>>>(RTOT, DIMM, MLPW,
                ff2, w22 + (size_t)l * DIMM * 2 * MLPW, b2 + l * DIMM, cur, cur);

        k_write_krep<<<(BB * KTOK * DIMM + 255) / 256, 256>>>(
                out + (size_t)l * BB * KTOK * DIMM, kmask);
    }

    k_write_clst<<<(BB * DIMM + 255) / 256, 256>>>(out + (size_t)DEPTHL * BB * KTOK * DIMM);
}

// round 8
// speedup vs baseline: 2.2286x; 1.0582x over previous
#include <cuda_runtime.h>
#include <cuda_bf16.h>
#include <math.h>
#include <stdint.h>

// ---------------- problem constants ----------------
#define BB    2
#define NTOK  4096
#define KTOK  144
#define DIMM  512
#define NHEAD 8
#define DH    64
#define QKVW  1536
#define MLPW  2048
#define DEPTHL 4
#define RTOT  (BB*NTOK + BB*KTOK + BB)   // 8482
#define KROW0 (BB*NTOK)                  // 8192
#define CROW0 (BB*NTOK + BB*KTOK)        // 8480
#define NEGBIG (-1e9f)
#define ATT_SCALE 0.125f                 // 64^-0.5

// ---------------- scratch ----------------
__device__ float d_cur[RTOT*DIMM];
__device__ float d_qkvb[RTOT*QKVW];
__device__ __align__(128) __nv_bfloat16 d_act2[RTOT*2*DIMM];
__device__ __align__(128) __nv_bfloat16 d_ff2[RTOT*2*MLPW];
__device__ __align__(128) __nv_bfloat16 d_wqkv2[DEPTHL*QKVW*2*DIMM];
__device__ __align__(128) __nv_bfloat16 d_wout2[DEPTHL*DIMM*2*DIMM];
__device__ __align__(128) __nv_bfloat16 d_w12[DEPTHL*MLPW*2*DIMM];
__device__ __align__(128) __nv_bfloat16 d_w22[DEPTHL*DIMM*2*MLPW];

// ---------------- helpers ----------------
__device__ __forceinline__ uint32_t smem_u32(const void* p) {
    uint32_t a;
    asm("{ .reg .u64 t; cvta.to.shared.u64 t, %1; cvt.u32.u64 %0, t; }" : "=r"(a) : "l"(p));
    return a;
}
#define SW128(x) ((x) ^ (((x) >> 3) & 0x70))

__device__ __forceinline__ void ldsm4(uint32_t* r, uint32_t addr) {
    asm volatile("ldmatrix.sync.aligned.m8n8.x4.shared.b16 {%0,%1,%2,%3}, [%4];"
        : "=r"(r[0]), "=r"(r[1]), "=r"(r[2]), "=r"(r[3]) : "r"(addr));
}
__device__ __forceinline__ void mma16816(float* c,
        uint32_t a0, uint32_t a1, uint32_t a2, uint32_t a3,
        uint32_t b0, uint32_t b1) {
    asm volatile("mma.sync.aligned.m16n8k16.row.col.f32.bf16.bf16.f32 "
        "{%0,%1,%2,%3}, {%4,%5,%6,%7}, {%8,%9}, {%0,%1,%2,%3};"
        : "+f"(c[0]), "+f"(c[1]), "+f"(c[2]), "+f"(c[3])
        : "r"(a0), "r"(a1), "r"(a2), "r"(a3), "r"(b0), "r"(b1));
}
__device__ __forceinline__ void cpasync16(uint32_t dst, const void* src, int srcsize) {
    asm volatile("cp.async.cg.shared.global [%0], [%1], 16, %2;"
        :: "r"(dst), "l"(src), "r"(srcsize) : "memory");
}
#define CP_COMMIT() asm volatile("cp.async.commit_group;" ::: "memory")
#define CP_WAIT2()  asm volatile("cp.async.wait_group 2;" ::: "memory")

__device__ __forceinline__ float gelu_exact(float v) {
    return 0.5f * v * (1.0f + erff(v * 0.70710678118654752f));
}
__device__ __forceinline__ void split_store_pair(__nv_bfloat16* base, size_t hi_idx,
                                                 int lo_off, float v0, float v1) {
    __nv_bfloat162 h, l;
    h.x = __float2bfloat16(v0);
    h.y = __float2bfloat16(v1);
    l.x = __float2bfloat16(v0 - __bfloat162float(h.x));
    l.y = __float2bfloat16(v1 - __bfloat162float(h.y));
    *(__nv_bfloat162*)&base[hi_idx] = h;
    *(__nv_bfloat162*)&base[hi_idx + lo_off] = l;
}

// ---------------- reduction helpers (256-thread blocks) ----------------
__device__ __forceinline__ float blockReduceSum256(float v) {
    __shared__ float sh[8];
    int lane = threadIdx.x & 31, w = threadIdx.x >> 5;
    #pragma unroll
    for (int o = 16; o; o >>= 1) v += __shfl_down_sync(0xffffffffu, v, o);
    if (lane == 0) sh[w] = v;
    __syncthreads();
    float r;
    if (threadIdx.x < 8) r = sh[threadIdx.x]; else r = 0.f;
    if (w == 0) {
        #pragma unroll
        for (int o = 4; o; o >>= 1) r += __shfl_down_sync(0xffu, r, o);
        if (lane == 0) sh[0] = r;
    }
    __syncthreads();
    r = sh[0];
    __syncthreads();
    return r;
}
__device__ __forceinline__ float blockReduceMax256(float v) {
    __shared__ float sh[8];
    int lane = threadIdx.x & 31, w = threadIdx.x >> 5;
    #pragma unroll
    for (int o = 16; o; o >>= 1) v = fmaxf(v, __shfl_down_sync(0xffffffffu, v, o));
    if (lane == 0) sh[w] = v;
    __syncthreads();
    float r;
    if (threadIdx.x < 8) r = sh[threadIdx.x]; else r = -INFINITY;
    if (w == 0) {
        #pragma unroll
        for (int o = 4; o; o >>= 1) r = fmaxf(r, __shfl_down_sync(0xffu, r, o));
        if (lane == 0) sh[0] = r;
    }
    __syncthreads();
    r = sh[0];
    __syncthreads();
    return r;
}

// ---------------- LayerNorm: warp per row, float4, fused split ----------------
// MODE 0: write fp32 to d_cur (destructive LN1) AND split bf16 to d_act2
// MODE 1: write split bf16 to d_act2 only
// INIT 1: source = concat(x, kx, clst) (layer-0 LN1)
template<int MODE, int INIT>
__global__ __launch_bounds__(256)
void k_layernorm(const float* __restrict__ g, const float* __restrict__ bp,
                 const float* __restrict__ x, const float* __restrict__ kx,
                 const float* __restrict__ clst) {
    int wid = threadIdx.x >> 5, lane = threadIdx.x & 31;
    int row = blockIdx.x * 8 + wid;
    if (row >= RTOT) return;
    const float* src;
    if (INIT) {
        if (row < KROW0)      src = x + (size_t)row * DIMM;
        else if (row < CROW0) src = kx + (size_t)(row - KROW0) * DIMM;
        else                  src = clst + (size_t)(row - CROW0) * DIMM;
    } else {
        src = d_cur + (size_t)row * DIMM;
    }
    float4 v[4];
    #pragma unroll
    for (int u = 0; u < 4; u++)
        v[u] = *(const float4*)&src[lane * 4 + u * 128];
    float s = 0.f;
    #pragma unroll
    for (int u = 0; u < 4; u++) s += v[u].x + v[u].y + v[u].z + v[u].w;
    #pragma unroll
    for (int o = 16; o; o >>= 1) s += __shfl_xor_sync(0xffffffffu, s, o);
    float mean = s * (1.0f / DIMM);
    float sq = 0.f;
    #pragma unroll
    for (int u = 0; u < 4; u++) {
        v[u].x -= mean; v[u].y -= mean; v[u].z -= mean; v[u].w -= mean;
        sq += v[u].x * v[u].x + v[u].y * v[u].y + v[u].z * v[u].z + v[u].w * v[u].w;
    }
    #pragma unroll
    for (int o = 16; o; o >>= 1) sq += __shfl_xor_sync(0xffffffffu, sq, o);
    float inv = rsqrtf(sq * (1.0f / DIMM) + 1e-5f);
    size_t base = (size_t)row * (2 * DIMM);
    #pragma unroll
    for (int u = 0; u < 4; u++) {
        int d = lane * 4 + u * 128;
        float4 gg = *(const float4*)&g[d];
        float4 bb = *(const float4*)&bp[d];
        float4 o;
        o.x = v[u].x * inv * gg.x + bb.x;
        o.y = v[u].y * inv * gg.y + bb.y;
        o.z = v[u].z * inv * gg.z + bb.z;
        o.w = v[u].w * inv * gg.w + bb.w;
        if (MODE == 0) *(float4*)&d_cur[(size_t)row * DIMM + d] = o;
        split_store_pair(d_act2, base + d,     DIMM, o.x, o.y);
        split_store_pair(d_act2, base + d + 2, DIMM, o.z, o.w);
    }
}

// ---------------- weight transpose + split (batched over layers) ----------------
__global__ void k_wsplit(const float* __restrict__ W0, __nv_bfloat16* __restrict__ WT0,
                         int K, int N) {
    __shared__ float t[32][33];
    const float* W = W0 + (size_t)blockIdx.z * K * N;
    __nv_bfloat16* WT = WT0 + (size_t)blockIdx.z * N * 2 * K;
    int k0 = blockIdx.y * 32, n0 = blockIdx.x * 32;
    int tx = threadIdx.x, ty = threadIdx.y;      // block (32,8)
    #pragma unroll
    for (int i = 0; i < 32; i += 8)
        t[ty + i][tx] = W[(size_t)(k0 + ty + i) * N + n0 + tx];
    __syncthreads();
    #pragma unroll
    for (int i = 0; i < 32; i += 8) {
        int n = n0 + ty + i, k = k0 + tx;
        float v = t[tx][ty + i];
        __nv_bfloat16 hi = __float2bfloat16(v);
        float lo = v - __bfloat162float(hi);
        WT[(size_t)n * (2 * K) + k]     = hi;
        WT[(size_t)n * (2 * K) + K + k] = __float2bfloat16(lo);
    }
}

// ---------------- HMMA bf16x3 GEMM (256x128 tile, cp.async 4-stage) ----------------
#define HBM 256
#define HABYTES (HBM*128)
#define HBBYTES (128*128)
#define HSTAGEB (HABYTES+HBBYTES)
#define HG_SMEM (4*HSTAGEB)      // 196608

template<int EPI>
__global__ __launch_bounds__(256, 1)
void k_hgemm(int M, int N, int Kh,
             const __nv_bfloat16* __restrict__ A2, const __nv_bfloat16* __restrict__ B2,
             const float* __restrict__ bias, const float* __restrict__ res,
             float* __restrict__ C) {
    extern __shared__ char smem[];
    uint32_t sb = smem_u32(smem);
    int tid = threadIdx.x, wid = tid >> 5, lane = tid & 31;
    int m0 = blockIdx.y * HBM, n0 = blockIdx.x * 128;
    int K2 = 2 * Kh;
    int wm = wid & 3, wn = wid >> 2;

    int ncc = Kh >> 6;
    int nch = 3 * ncc;

    int arow_g = m0 + tid;
    int asz = (arow_g < M) ? 16 : 0;
    const char* arow = (const char*)(A2 + (size_t)((arow_g < M) ? arow_g : (M - 1)) * K2);
    int brw = tid >> 1, bh = tid & 1;
    const char* brow = (const char*)(B2 + (size_t)(n0 + brw) * K2) + bh * 64;

    auto load_chunk = [&](int stg, int c) {
        int seg = c / ncc;
        int cc  = c - seg * ncc;
        int aoff = ((seg == 2) ? Kh : 0) + (cc << 6);
        int boff = ((seg == 1) ? Kh : 0) + (cc << 6);
        uint32_t abase = sb + stg * HSTAGEB;
        uint32_t bbase = abase + HABYTES;
        const char* asrc = arow + (size_t)aoff * 2;
        #pragma unroll
        for (int u = 0; u < 8; u++)
            cpasync16(abase + SW128(tid * 128 + u * 16), asrc + u * 16, asz);
        const char* bsrc = brow + (size_t)boff * 2;
        #pragma unroll
        for (int u = 0; u < 4; u++)
            cpasync16(bbase + SW128(brw * 128 + bh * 64 + u * 16), bsrc + u * 16, 16);
    };

    float acc[4][8][4];
    #pragma unroll
    for (int i = 0; i < 4; i++)
        #pragma unroll
        for (int j = 0; j < 8; j++)
            #pragma unroll
            for (int q = 0; q < 4; q++) acc[i][j][q] = 0.f;

    load_chunk(0, 0); CP_COMMIT();
    load_chunk(1, 1); CP_COMMIT();
    load_chunk(2, 2); CP_COMMIT();

    int a_row_l = wm * 64 + (lane & 15);
    int a_kb_l  = (lane >> 4) * 16;
    int b_row_l = wn * 64 + (lane & 7) + ((lane >> 4) << 3);
    int b_kb_l  = ((lane >> 3) & 1) * 16;

    for (int c = 0; c < nch; c++) {
        CP_WAIT2();
        __syncthreads();
        uint32_t au = sb + (c & 3) * HSTAGEB;
        uint32_t bu = au + HABYTES;
        #pragma unroll
        for (int s = 0; s < 4; s++) {
            uint32_t af[4][4], bf[4][4];
            #pragma unroll
            for (int mf = 0; mf < 4; mf++)
                ldsm4(af[mf], au + SW128((a_row_l + mf * 16) * 128 + s * 32 + a_kb_l));
            #pragma unroll
            for (int np = 0; np < 4; np++)
                ldsm4(bf[np], bu + SW128((b_row_l + np * 16) * 128 + s * 32 + b_kb_l));
            #pragma unroll
            for (int mf = 0; mf < 4; mf++)
                #pragma unroll
                for (int np = 0; np < 4; np++) {
                    mma16816(acc[mf][np * 2 + 0], af[mf][0], af[mf][1], af[mf][2], af[mf][3],
                             bf[np][0], bf[np][1]);
                    mma16816(acc[mf][np * 2 + 1], af[mf][0], af[mf][1], af[mf][2], af[mf][3],
                             bf[np][2], bf[np][3]);
                }
        }
        int cn = c + 3;
        if (cn < nch) { load_chunk(cn & 3, cn); CP_COMMIT(); }
    }

    #pragma unroll
    for (int mf = 0; mf < 4; mf++) {
        #pragma unroll
        for (int nf = 0; nf < 8; nf++) {
            int col = n0 + wn * 64 + nf * 8 + (lane & 3) * 2;
            #pragma unroll
            for (int hrow = 0; hrow < 2; hrow++) {
                int row = m0 + wm * 64 + mf * 16 + hrow * 8 + (lane >> 2);
                if (row >= M) continue;
                float v0 = acc[mf][nf][hrow * 2 + 0];
                float v1 = acc[mf][nf][hrow * 2 + 1];
                if (EPI >= 1) {
                    float2 bb = *(const float2*)&bias[col];
                    v0 += bb.x; v1 += bb.y;
                }
                if (EPI == 2) {
                    v0 = gelu_exact(v0); v1 = gelu_exact(v1);
                    split_store_pair((__nv_bfloat16*)C, (size_t)row * (2 * N) + col, N, v0, v1);
                } else {
                    size_t o = (size_t)row * N + col;
                    if (EPI == 1) {
                        float2 rr = *(const float2*)&res[o];
                        v0 += rr.x; v1 += rr.y;
                    }
                    float2 w; w.x = v0; w.y = v1;
                    *(float2*)&C[o] = w;
                }
            }
        }
    }
}

// ---------------- patch -> kernel attention ----------------
#define PAD 68
__global__ void k_attn_patch(const float* __restrict__ rd,
                             const float* __restrict__ mask, const float* __restrict__ kmask,
                             float inv_denom) {
    extern __shared__ float sm[];
    float* Ks = sm;
    float* Qs = Ks + KTOK * PAD;
    float* Sc = Qs + 32 * PAD;
    int b = blockIdx.z, h = blockIdx.y;
    int i0 = blockIdx.x * 32;
    int tid = threadIdx.x;
    const float* qkv = d_qkvb;

    for (int idx = tid; idx < KTOK * 16; idx += 256) {
        int j = idx >> 4, d = (idx & 15) * 4;
        *(float4*)&Ks[j * PAD + d] =
            *(const float4*)&qkv[(size_t)(KROW0 + b * KTOK + j) * QKVW + DIMM + h * DH + d];
    }
    for (int idx = tid; idx < 32 * 16; idx += 256) {
        int i = idx >> 4, d = (idx & 15) * 4;
        *(float4*)&Qs[i * PAD + d] =
            *(const float4*)&qkv[(size_t)(b * NTOK + i0 + i) * QKVW + h * DH + d];
    }
    __syncthreads();

    int warp = tid >> 5, lane = tid & 31;
    #pragma unroll
    for (int qi = 0; qi < 4; qi++) {
        int i = warp * 4 + qi;
        float mi = mask[b * NTOK + i0 + i];
        for (int j = lane; j < KTOK; j += 32) {
            float dot = 0.f;
            #pragma unroll
            for (int d = 0; d < DH; d += 4) {
                float4 q = *(float4*)&Qs[i * PAD + d];
                float4 k = *(float4*)&Ks[j * PAD + d];
                dot += q.x * k.x + q.y * k.y + q.z * k.z + q.w * k.w;
            }
            float s = (mi * kmask[b * KTOK + j] < 0.5f) ? NEGBIG : dot * ATT_SCALE;
            Sc[i * KTOK + j] = s;
        }
        float m = -INFINITY;
        for (int j = lane; j < KTOK; j += 32) m = fmaxf(m, Sc[i * KTOK + j]);
        #pragma unroll
        for (int o = 16; o; o >>= 1) m = fmaxf(m, __shfl_xor_sync(0xffffffffu, m, o));
        float ssum = 0.f;
        for (int j = lane; j < KTOK; j += 32) {
            float e = expf(Sc[i * KTOK + j] - m);
            Sc[i * KTOK + j] = e;
            ssum += e;
        }
        #pragma unroll
        for (int o = 16; o; o >>= 1) ssum += __shfl_xor_sync(0xffffffffu, ssum, o);
        float invs = 1.0f / ssum;
        for (int j = lane; j < KTOK; j += 32) {
            float r = rd[(size_t)b * KTOK * NTOK + (size_t)j * NTOK + i0 + i];
            Sc[i * KTOK + j] *= invs * expf(-r * r * inv_denom);
        }
    }
    __syncthreads();

    for (int idx = tid; idx < KTOK * 16; idx += 256) {
        int j = idx >> 4, d = (idx & 15) * 4;
        *(float4*)&Ks[j * PAD + d] =
            *(const float4*)&qkv[(size_t)(KROW0 + b * KTOK + j) * QKVW + 2 * DIMM + h * DH + d];
    }
    __syncthreads();

    int i = tid >> 3;
    int d0 = (tid & 7) * 8;
    float acc[8] = {0.f,0.f,0.f,0.f,0.f,0.f,0.f,0.f};
    for (int j = 0; j < KTOK; j++) {
        float p = Sc[i * KTOK + j];
        float4 v0 = *(float4*)&Ks[j * PAD + d0];
        float4 v1 = *(float4*)&Ks[j * PAD + d0 + 4];
        acc[0] += p * v0.x; acc[1] += p * v0.y; acc[2] += p * v0.z; acc[3] += p * v0.w;
        acc[4] += p * v1.x; acc[5] += p * v1.y; acc[6] += p * v1.z; acc[7] += p * v1.w;
    }
    size_t row = (size_t)(b * NTOK + i0 + i);
    size_t base = row * (2 * DIMM) + h * DH + d0;
    #pragma unroll
    for (int u = 0; u < 4; u++)
        split_store_pair(d_act2, base + 2 * u, DIMM, acc[2 * u], acc[2 * u + 1]);
}

// ---------------- kernel -> patch attention (flash-style tiles) ----------------
#define FTK 16
#define FTN 64
#define KP  68
__global__ __launch_bounds__(256)
void k_attn_kside(const float* __restrict__ rd,
                  const float* __restrict__ mask, const float* __restrict__ kmask,
                  float inv_denom) {
    __shared__ float Qs[FTK][KP];
    __shared__ float Ks[FTN][KP];
    __shared__ float Vs[FTN][KP];
    __shared__ float Ps[FTK][FTN];
    __shared__ float kmrow[FTK];
    int ik0 = blockIdx.x * FTK, h = blockIdx.y, b = blockIdx.z;
    int tid = threadIdx.x;
    int ik = tid >> 4, sub = tid & 15;
    const float* qkv = d_qkvb;

    {
        int r = tid >> 4, d = (tid & 15) * 4;
        *(float4*)&Qs[r][d] =
            *(const float4*)&qkv[(size_t)(KROW0 + b * KTOK + ik0 + r) * QKVW + h * DH + d];
        if (tid < FTK) kmrow[tid] = kmask[b * KTOK + ik0 + tid];
    }
    __syncthreads();
    float kmi = kmrow[ik];
    const float* rdrow = rd + (size_t)b * KTOK * NTOK + (size_t)(ik0 + ik) * NTOK;

    float m_run = -INFINITY, l_run = 0.f;
    float a0 = 0.f, a1 = 0.f, a2 = 0.f, a3 = 0.f;

    for (int n0 = 0; n0 < NTOK; n0 += FTN) {
        {
            int r = tid >> 2, d = (tid & 3) * 16;
            const float* kp = &qkv[(size_t)(b * NTOK + n0 + r) * QKVW + DIMM + h * DH + d];
            const float* vp = &qkv[(size_t)(b * NTOK + n0 + r) * QKVW + 2 * DIMM + h * DH + d];
            #pragma unroll
            for (int u = 0; u < 4; u++) {
                *(float4*)&Ks[r][d + u * 4] = *(const float4*)(kp + u * 4);
                *(float4*)&Vs[r][d + u * 4] = *(const float4*)(vp + u * 4);
            }
        }
        __syncthreads();

        float s[4] = {0.f, 0.f, 0.f, 0.f};
        #pragma unroll
        for (int d = 0; d < DH; d += 4) {
            float4 q = *(float4*)&Qs[ik][d];
            #pragma unroll
            for (int jj = 0; jj < 4; jj++) {
                float4 k = *(float4*)&Ks[sub + jj * 16][d];
                s[jj] += q.x * k.x + q.y * k.y + q.z * k.z + q.w * k.w;
            }
        }
        float tmax = -INFINITY;
        #pragma unroll
        for (int jj = 0; jj < 4; jj++) {
            int jg = n0 + sub + jj * 16;
            s[jj] = (mask[b * NTOK + jg] * kmi < 0.5f) ? NEGBIG : s[jj] * ATT_SCALE;
            tmax = fmaxf(tmax, s[jj]);
        }
        #pragma unroll
        for (int o = 8; o; o >>= 1)
            tmax = fmaxf(tmax, __shfl_xor_sync(0xffffffffu, tmax, o, 16));
        float m_new = fmaxf(m_run, tmax);
        float scale = expf(m_run - m_new);
        float tsum = 0.f;
        #pragma unroll
        for (int jj = 0; jj < 4; jj++) {
            float e = expf(s[jj] - m_new);
            tsum += e;
            int j = sub + jj * 16;
            float r = rdrow[n0 + j];
            Ps[ik][j] = e * expf(-r * r * inv_denom);
        }
        #pragma unroll
        for (int o = 8; o; o >>= 1)
            tsum += __shfl_xor_sync(0xffffffffu, tsum, o, 16);
        l_run = l_run * scale + tsum;
        m_run = m_new;
        __syncwarp();

        a0 *= scale; a1 *= scale; a2 *= scale; a3 *= scale;
        int d = sub * 4;
        #pragma unroll 8
        for (int j = 0; j < FTN; j++) {
            float p = Ps[ik][j];
            float4 v = *(float4*)&Vs[j][d];
            a0 += p * v.x; a1 += p * v.y; a2 += p * v.z; a3 += p * v.w;
        }
        __syncthreads();
    }

    float invl = 1.0f / l_run;
    size_t row = (size_t)(KROW0 + b * KTOK + ik0 + ik);
    size_t base = row * (2 * DIMM) + h * DH + sub * 4;
    split_store_pair(d_act2, base,     DIMM, a0 * invl, a1 * invl);
    split_store_pair(d_act2, base + 2, DIMM, a2 * invl, a3 * invl);
}

// ---------------- clst -> kernel attention ----------------
__global__ void k_attn_clst(const float* __restrict__ mask,
                            const float* __restrict__ kmask) {
    __shared__ float Qc[DH];
    __shared__ float Sc[KTOK];
    int h = blockIdx.x, b = blockIdx.y;
    int tid = threadIdx.x;
    const float* qkv = d_qkvb;
    size_t qrow = (size_t)(CROW0 + b);
    if (tid < DH) Qc[tid] = qkv[qrow * QKVW + h * DH + tid];
    __syncthreads();
    float m0 = mask[b * NTOK];
    float s = -INFINITY;
    if (tid < KTOK) {
        const float4* kp = (const float4*)&qkv[(size_t)(KROW0 + b * KTOK + tid) * QKVW + DIMM + h * DH];
        float dot = 0.f;
        #pragma unroll
        for (int d4 = 0; d4 < 16; d4++) {
            float4 kv = kp[d4];
            dot += Qc[d4*4+0]*kv.x + Qc[d4*4+1]*kv.y + Qc[d4*4+2]*kv.z + Qc[d4*4+3]*kv.w;
        }
        s = (m0 * kmask[b * KTOK + tid] < 0.5f) ? NEGBIG : dot * ATT_SCALE;
        Sc[tid] = s;
    }
    float M = blockReduceMax256(s);
    float e = 0.f;
    if (tid < KTOK) {
        e = expf(s - M);
        Sc[tid] = e;
    }
    float S = blockReduceSum256(e);
    float invS = 1.0f / S;
    if (tid < DH) {
        float a = 0.f;
        for (int j = 0; j < KTOK; j++)
            a += Sc[j] * qkv[(size_t)(KROW0 + b * KTOK + j) * QKVW + 2 * DIMM + h * DH + tid];
        a *= invS;
        size_t base = qrow * (2 * DIMM) + h * DH + tid;
        __nv_bfloat16 hi = __float2bfloat16(a);
        d_act2[base] = hi;
        d_act2[base + DIMM] = __float2bfloat16(a - __bfloat162float(hi));
    }
}

// ---------------- output writes ----------------
__global__ void k_write_krep(float* __restrict__ out, const float* __restrict__ kmask) {
    int idx = blockIdx.x * blockDim.x + threadIdx.x;
    if (idx >= BB * KTOK * DIMM) return;
    int d = idx & 511;
    int row = idx >> 9;
    float km = kmask[row];
    out[idx] = (km < 0.5f) ? 0.f : d_cur[(size_t)(KROW0 + row) * DIMM + d];
}
__global__ void k_write_clst(float* __restrict__ out) {
    int idx = blockIdx.x * blockDim.x + threadIdx.x;
    if (idx >= BB * DIMM) return;
    int b = idx >> 9, d = idx & 511;
    out[idx] = d_cur[(size_t)(CROW0 + b) * DIMM + d];
}

// ---------------- launcher ----------------
extern "C" void kernel_launch(void* const* d_in, const int* in_sizes, int n_in,
                              void* d_out, int out_size) {
    const float* x     = (const float*)d_in[0];
    const float* kx    = (const float*)d_in[1];
    const float* rd    = (const float*)d_in[2];
    const float* clst  = (const float*)d_in[3];
    const float* mask  = (const float*)d_in[4];
    const float* kmask = (const float*)d_in[5];
    const float* ln1_g = (const float*)d_in[6];
    const float* ln1_b = (const float*)d_in[7];
    const float* w_qkv = (const float*)d_in[8];
    const float* w_out = (const float*)d_in[9];
    const float* b_out = (const float*)d_in[10];
    const float* ln2_g = (const float*)d_in[11];
    const float* ln2_b = (const float*)d_in[12];
    const float* w1    = (const float*)d_in[13];
    const float* b1    = (const float*)d_in[14];
    const float* w2    = (const float*)d_in[15];
    const float* b2    = (const float*)d_in[16];
    float* out = (float*)d_out;

    static float *cur = nullptr, *qkvb = nullptr;
    static __nv_bfloat16 *act2 = nullptr, *ff2 = nullptr;
    static __nv_bfloat16 *wqkv2 = nullptr, *wout2 = nullptr, *w12 = nullptr, *w22 = nullptr;
    if (!cur) {
        cudaGetSymbolAddress((void**)&cur,   d_cur);
        cudaGetSymbolAddress((void**)&qkvb,  d_qkvb);
        cudaGetSymbolAddress((void**)&act2,  d_act2);
        cudaGetSymbolAddress((void**)&ff2,   d_ff2);
        cudaGetSymbolAddress((void**)&wqkv2, d_wqkv2);
        cudaGetSymbolAddress((void**)&wout2, d_wout2);
        cudaGetSymbolAddress((void**)&w12,   d_w12);
        cudaGetSymbolAddress((void**)&w22,   d_w22);
        int patch_smem = (KTOK * PAD + 32 * PAD + 32 * KTOK) * (int)sizeof(float);
        cudaFuncSetAttribute(k_attn_patch, cudaFuncAttributeMaxDynamicSharedMemorySize, patch_smem);
        cudaFuncSetAttribute(k_hgemm<0>, cudaFuncAttributeMaxDynamicSharedMemorySize, HG_SMEM);
        cudaFuncSetAttribute(k_hgemm<1>, cudaFuncAttributeMaxDynamicSharedMemorySize, HG_SMEM);
        cudaFuncSetAttribute(k_hgemm<2>, cudaFuncAttributeMaxDynamicSharedMemorySize, HG_SMEM);
    }
    int patch_smem = (KTOK * PAD + 32 * PAD + 32 * KTOK) * (int)sizeof(float);

    int mt = (RTOT + HBM - 1) / HBM;   // 34
    int lnb = (RTOT + 7) / 8;          // 1061
    dim3 wblk(32, 8);

    // weight transpose+split: 4 launches, batched over layers (launches 0-3)
    k_wsplit<<<dim3(QKVW / 32, DIMM / 32, DEPTHL), wblk>>>(w_qkv, wqkv2, DIMM, QKVW);
    k_wsplit<<<dim3(DIMM / 32, DIMM / 32, DEPTHL), wblk>>>(w_out, wout2, DIMM, DIMM);
    k_wsplit<<<dim3(MLPW / 32, DIMM / 32, DEPTHL), wblk>>>(w1, w12, DIMM, MLPW);
    k_wsplit<<<dim3(DIMM / 32, MLPW / 32, DEPTHL), wblk>>>(w2, w22, MLPW, DIMM);

    for (int l = 0; l < DEPTHL; l++) {
        float inv_denom = 1.0f / (64.0f * (float)(1 << l));

        // LN1 (layer 0 fuses the input concat; launch 4)
        if (l == 0)
            k_layernorm<0, 1><<<lnb, 256>>>(ln1_g, ln1_b, x, kx, clst);
        else
            k_layernorm<0, 0><<<lnb, 256>>>(ln1_g + l * DIMM, ln1_b + l * DIMM,
                                            nullptr, nullptr, nullptr);

        // QKV projection (launch 5 on first layer -> profiled by ncu -s 5 -c 1)
        k_hgemm<0><<<dim3(QKVW / 128, mt), 256, HG_SMEM>>>(RTOT, QKVW, DIMM,
                act2, wqkv2 + (size_t)l * QKVW * 2 * DIMM, nullptr, nullptr, qkvb);

        // attentions -> act2 split
        k_attn_patch<<<dim3(NTOK / 32, NHEAD, BB), 256, patch_smem>>>(rd, mask, kmask, inv_denom);
        k_attn_kside<<<dim3(KTOK / FTK, NHEAD, BB), 256>>>(rd, mask, kmask, inv_denom);
        k_attn_clst<<<dim3(NHEAD, BB), 256>>>(mask, kmask);

        // out projection + residual -> cur fp32
        k_hgemm<1><<<dim3(DIMM / 128, mt), 256, HG_SMEM>>>(RTOT, DIMM, DIMM,
                act2, wout2 + (size_t)l * DIMM * 2 * DIMM, b_out + l * DIMM, cur, cur);

        // FFN
        k_layernorm<1, 0><<<lnb, 256>>>(ln2_g + l * DIMM, ln2_b + l * DIMM,
                                        nullptr, nullptr, nullptr);
        k_hgemm<2><<<dim3(MLPW / 128, mt), 256, HG_SMEM>>>(RTOT, MLPW, DIMM,
                act2, w12 + (size_t)l * MLPW * 2 * DIMM, b1 + l * MLPW, nullptr, (float*)ff2);
        k_hgemm<1><<<dim3(DIMM / 128, mt), 256, HG_SMEM>>>(RTOT, DIMM, MLPW,
                ff2, w22 + (size_t)l * DIMM * 2 * MLPW, b2 + l * DIMM, cur, cur);

        k_write_krep<<<(BB * KTOK * DIMM + 255) / 256, 256>>>(
                out + (size_t)l * BB * KTOK * DIMM, kmask);
    }

    k_write_clst<<<(BB * DIMM + 255) / 256, 256>>>(out + (size_t)DEPTHL * BB * KTOK * DIMM);
}